// round 2
// baseline (speedup 1.0000x reference)
#include <cuda_runtime.h>
#include <math.h>

#define SEQ   2048
#define BATCH 4
#define EMB   768
#define NHEAD 12
#define DH    64
#define ROWS  (SEQ*BATCH)   // 8192

// ---------------- scratch (device globals; allocation-free) ----------------
__device__ float g_h[ROWS * EMB];          // LN output (reused ln1/ln2)
__device__ float g_qkv[ROWS * 3 * EMB];    // qkv
__device__ float g_attn[ROWS * EMB];       // attention output
__device__ float g_x1[ROWS * EMB];         // x + attn_out
__device__ float g_f[ROWS * 4 * EMB];      // MLP hidden

// ---------------- LayerNorm ----------------
__inline__ __device__ float warp_sum(float v) {
    #pragma unroll
    for (int o = 16; o; o >>= 1) v += __shfl_xor_sync(0xffffffffu, v, o);
    return v;
}

__global__ void __launch_bounds__(256) ln_kernel(
    const float* __restrict__ x, const float* __restrict__ w,
    const float* __restrict__ b, float* __restrict__ y)
{
    __shared__ float rs[8], rq[8];
    __shared__ float s_mean, s_rstd;
    int row = blockIdx.x;
    int tid = threadIdx.x;
    const float* xr = x + (size_t)row * EMB;
    float v0 = xr[tid], v1 = xr[tid + 256], v2 = xr[tid + 512];
    float s = v0 + v1 + v2;
    float q = v0*v0 + v1*v1 + v2*v2;
    s = warp_sum(s); q = warp_sum(q);
    int wid = tid >> 5, lane = tid & 31;
    if (lane == 0) { rs[wid] = s; rq[wid] = q; }
    __syncthreads();
    if (tid == 0) {
        float S = 0.f, Q = 0.f;
        #pragma unroll
        for (int i = 0; i < 8; i++) { S += rs[i]; Q += rq[i]; }
        float mean = S * (1.0f / EMB);
        float var  = Q * (1.0f / EMB) - mean * mean;
        s_mean = mean;
        s_rstd = rsqrtf(var + 1e-5f);
    }
    __syncthreads();
    float mean = s_mean, rstd = s_rstd;
    float* yr = y + (size_t)row * EMB;
    yr[tid]       = (v0 - mean) * rstd * w[tid]       + b[tid];
    yr[tid + 256] = (v1 - mean) * rstd * w[tid + 256] + b[tid + 256];
    yr[tid + 512] = (v2 - mean) * rstd * w[tid + 512] + b[tid + 512];
}

// ---------------- GEMM: C[M,N] = A[M,K] @ B[N,K]^T + bias (+res / +QuickGELU) ----------------
// BM=BN=128, BK=16, 256 threads, 8x8 microtile.
// MODE: 0 = bias, 1 = bias + residual, 2 = bias + QuickGELU
template<int MODE>
__global__ void __launch_bounds__(256) gemm_kernel(
    const float* __restrict__ A, const float* __restrict__ B,
    const float* __restrict__ bias, const float* __restrict__ res,
    float* __restrict__ C, int M, int N, int K)
{
    __shared__ float As[16][128];
    __shared__ float Bs[16][128];
    int tid = threadIdx.x;
    int tx = tid & 15, ty = tid >> 4;
    int m0 = blockIdx.y * 128, n0 = blockIdx.x * 128;
    int lr = tid >> 1;            // 0..127
    int lk = (tid & 1) * 8;       // 0 or 8
    const float* Ap = A + (size_t)(m0 + lr) * K + lk;
    const float* Bp = B + (size_t)(n0 + lr) * K + lk;

    float acc[8][8];
    #pragma unroll
    for (int i = 0; i < 8; i++)
        #pragma unroll
        for (int j = 0; j < 8; j++) acc[i][j] = 0.f;

    for (int k0 = 0; k0 < K; k0 += 16) {
        float4 a0 = *(const float4*)(Ap + k0);
        float4 a1 = *(const float4*)(Ap + k0 + 4);
        float4 b0 = *(const float4*)(Bp + k0);
        float4 b1 = *(const float4*)(Bp + k0 + 4);
        As[lk+0][lr]=a0.x; As[lk+1][lr]=a0.y; As[lk+2][lr]=a0.z; As[lk+3][lr]=a0.w;
        As[lk+4][lr]=a1.x; As[lk+5][lr]=a1.y; As[lk+6][lr]=a1.z; As[lk+7][lr]=a1.w;
        Bs[lk+0][lr]=b0.x; Bs[lk+1][lr]=b0.y; Bs[lk+2][lr]=b0.z; Bs[lk+3][lr]=b0.w;
        Bs[lk+4][lr]=b1.x; Bs[lk+5][lr]=b1.y; Bs[lk+6][lr]=b1.z; Bs[lk+7][lr]=b1.w;
        __syncthreads();
        #pragma unroll
        for (int kk = 0; kk < 16; kk++) {
            float a[8], bb[8];
            *(float4*)&a[0]  = *(const float4*)&As[kk][ty*8];
            *(float4*)&a[4]  = *(const float4*)&As[kk][ty*8 + 4];
            *(float4*)&bb[0] = *(const float4*)&Bs[kk][tx*8];
            *(float4*)&bb[4] = *(const float4*)&Bs[kk][tx*8 + 4];
            #pragma unroll
            for (int i = 0; i < 8; i++)
                #pragma unroll
                for (int j = 0; j < 8; j++)
                    acc[i][j] = fmaf(a[i], bb[j], acc[i][j]);
        }
        __syncthreads();
    }

    #pragma unroll
    for (int i = 0; i < 8; i++) {
        int row = m0 + ty*8 + i;
        #pragma unroll
        for (int j = 0; j < 8; j++) {
            int col = n0 + tx*8 + j;
            float v = acc[i][j] + bias[col];
            if (MODE == 1) v += res[(size_t)row * N + col];
            if (MODE == 2) v = v / (1.0f + __expf(-1.702f * v));
            C[(size_t)row * N + col] = v;
        }
    }
}

// ---------------- Flash-style attention ----------------
// grid: (SEQ/64, BATCH*NHEAD); 256 threads (16x16, 4x4 microtile)
// smem: Qs[d][q] 16KB, Ks[d][k] 16KB, Vs[kv][d] 16KB, Ss[q][kv] 16KB,
//       red[64][17], m/l/f rows.
#define ATTN_RED_STRIDE 17
#define ATTN_SMEM_FLOATS (4*64*64 + 64*ATTN_RED_STRIDE + 3*64)
#define ATTN_SMEM_BYTES  (ATTN_SMEM_FLOATS * 4)

__global__ void __launch_bounds__(256) attn_kernel(
    const float* __restrict__ qkv, float* __restrict__ out)
{
    extern __shared__ float sm[];
    float* Qs   = sm;                 // [64 d][64 q]
    float* Ks   = sm + 4096;          // [64 d][64 k]
    float* Vs   = sm + 8192;          // [64 kv][64 d]
    float* Ss   = sm + 12288;         // [64 q][64 kv]
    float* red  = sm + 16384;         // [64][17]
    float* mrow = sm + 16384 + 64*ATTN_RED_STRIDE;
    float* lrow = mrow + 64;
    float* frow = lrow + 64;

    int tid = threadIdx.x;
    int tx = tid & 15, ty = tid >> 4;
    int nh = blockIdx.y;
    int n = nh / NHEAD, h = nh % NHEAD;
    int q0 = blockIdx.x * 64;
    int qr = tid >> 2;                // 0..63
    int d4 = (tid & 3) * 16;          // 0,16,32,48

    // load Q tile transposed, pre-scaled by 1/sqrt(Dh)
    {
        const float* qp = qkv + ((size_t)(q0 + qr) * BATCH + n) * (3*EMB) + h*DH + d4;
        #pragma unroll
        for (int i = 0; i < 4; i++) {
            float4 v = *(const float4*)(qp + i*4);
            Qs[(d4+i*4+0)*64 + qr] = v.x * 0.125f;
            Qs[(d4+i*4+1)*64 + qr] = v.y * 0.125f;
            Qs[(d4+i*4+2)*64 + qr] = v.z * 0.125f;
            Qs[(d4+i*4+3)*64 + qr] = v.w * 0.125f;
        }
    }
    if (tid < 64) { mrow[tid] = -1e30f; lrow[tid] = 0.f; }

    float o[4][4];
    #pragma unroll
    for (int i = 0; i < 4; i++)
        #pragma unroll
        for (int j = 0; j < 4; j++) o[i][j] = 0.f;

    for (int t0 = 0; t0 < SEQ; t0 += 64) {
        __syncthreads();   // protects Ks/Vs/red/frow from previous iteration use
        // load K (transposed) and V tiles
        {
            const float* kp = qkv + ((size_t)(t0 + qr) * BATCH + n) * (3*EMB) + EMB + h*DH + d4;
            const float* vp = kp + EMB;
            #pragma unroll
            for (int i = 0; i < 4; i++) {
                float4 kv4 = *(const float4*)(kp + i*4);
                Ks[(d4+i*4+0)*64 + qr] = kv4.x;
                Ks[(d4+i*4+1)*64 + qr] = kv4.y;
                Ks[(d4+i*4+2)*64 + qr] = kv4.z;
                Ks[(d4+i*4+3)*64 + qr] = kv4.w;
                float4 vv = *(const float4*)(vp + i*4);
                *(float4*)&Vs[qr*64 + d4 + i*4] = vv;
            }
        }
        __syncthreads();

        // S = (Q*scale) @ K^T : 4x4 fragment
        float s[4][4];
        #pragma unroll
        for (int i = 0; i < 4; i++)
            #pragma unroll
            for (int j = 0; j < 4; j++) s[i][j] = 0.f;
        #pragma unroll 16
        for (int d = 0; d < 64; d++) {
            float4 a  = *(const float4*)&Qs[d*64 + ty*4];
            float4 bq = *(const float4*)&Ks[d*64 + tx*4];
            float aa[4] = {a.x, a.y, a.z, a.w};
            float bb[4] = {bq.x, bq.y, bq.z, bq.w};
            #pragma unroll
            for (int i = 0; i < 4; i++)
                #pragma unroll
                for (int j = 0; j < 4; j++)
                    s[i][j] = fmaf(aa[i], bb[j], s[i][j]);
        }

        // per-fragment row max
        #pragma unroll
        for (int i = 0; i < 4; i++) {
            float lm = fmaxf(fmaxf(s[i][0], s[i][1]), fmaxf(s[i][2], s[i][3]));
            red[(ty*4+i)*ATTN_RED_STRIDE + tx] = lm;
        }
        __syncthreads();
        if (tid < 64) {
            float tm = red[tid*ATTN_RED_STRIDE];
            #pragma unroll
            for (int k2 = 1; k2 < 16; k2++) tm = fmaxf(tm, red[tid*ATTN_RED_STRIDE + k2]);
            float mo = mrow[tid], mn = fmaxf(mo, tm);
            frow[tid] = __expf(mo - mn);
            mrow[tid] = mn;
        }
        __syncthreads();

        // p = exp(s - m), partial row sums, stash P
        #pragma unroll
        for (int i = 0; i < 4; i++) {
            float mn = mrow[ty*4+i];
            float p0 = __expf(s[i][0] - mn);
            float p1 = __expf(s[i][1] - mn);
            float p2 = __expf(s[i][2] - mn);
            float p3 = __expf(s[i][3] - mn);
            *(float4*)&Ss[(ty*4+i)*64 + tx*4] = make_float4(p0, p1, p2, p3);
            red[(ty*4+i)*ATTN_RED_STRIDE + tx] = p0 + p1 + p2 + p3;
        }
        __syncthreads();
        if (tid < 64) {
            float su = 0.f;
            #pragma unroll
            for (int k2 = 0; k2 < 16; k2++) su += red[tid*ATTN_RED_STRIDE + k2];
            lrow[tid] = lrow[tid] * frow[tid] + su;
        }

        // rescale O, accumulate P @ V
        float f0 = frow[ty*4+0], f1 = frow[ty*4+1], f2 = frow[ty*4+2], f3 = frow[ty*4+3];
        #pragma unroll
        for (int j = 0; j < 4; j++) {
            o[0][j] *= f0; o[1][j] *= f1; o[2][j] *= f2; o[3][j] *= f3;
        }
        #pragma unroll 16
        for (int kk = 0; kk < 64; kk++) {
            float4 bv = *(const float4*)&Vs[kk*64 + tx*4];
            float a0 = Ss[(ty*4+0)*64 + kk];
            float a1 = Ss[(ty*4+1)*64 + kk];
            float a2 = Ss[(ty*4+2)*64 + kk];
            float a3 = Ss[(ty*4+3)*64 + kk];
            o[0][0] = fmaf(a0, bv.x, o[0][0]); o[0][1] = fmaf(a0, bv.y, o[0][1]);
            o[0][2] = fmaf(a0, bv.z, o[0][2]); o[0][3] = fmaf(a0, bv.w, o[0][3]);
            o[1][0] = fmaf(a1, bv.x, o[1][0]); o[1][1] = fmaf(a1, bv.y, o[1][1]);
            o[1][2] = fmaf(a1, bv.z, o[1][2]); o[1][3] = fmaf(a1, bv.w, o[1][3]);
            o[2][0] = fmaf(a2, bv.x, o[2][0]); o[2][1] = fmaf(a2, bv.y, o[2][1]);
            o[2][2] = fmaf(a2, bv.z, o[2][2]); o[2][3] = fmaf(a2, bv.w, o[2][3]);
            o[3][0] = fmaf(a3, bv.x, o[3][0]); o[3][1] = fmaf(a3, bv.y, o[3][1]);
            o[3][2] = fmaf(a3, bv.z, o[3][2]); o[3][3] = fmaf(a3, bv.w, o[3][3]);
        }
    }
    __syncthreads();   // lrow final values visible to all

    #pragma unroll
    for (int i = 0; i < 4; i++) {
        float inv = 1.0f / lrow[ty*4+i];
        float* op = out + ((size_t)(q0 + ty*4 + i) * BATCH + n) * EMB + h*DH + tx*4;
        *(float4*)op = make_float4(o[i][0]*inv, o[i][1]*inv, o[i][2]*inv, o[i][3]*inv);
    }
}

// ---------------- launch ----------------
extern "C" void kernel_launch(void* const* d_in, const int* in_sizes, int n_in,
                              void* d_out, int out_size)
{
    const float* x      = (const float*)d_in[0];
    const float* ln1_w  = (const float*)d_in[1];
    const float* ln1_b  = (const float*)d_in[2];
    const float* w_qkv  = (const float*)d_in[3];
    const float* b_qkv  = (const float*)d_in[4];
    const float* w_out  = (const float*)d_in[5];
    const float* b_out  = (const float*)d_in[6];
    const float* ln2_w  = (const float*)d_in[7];
    const float* ln2_b  = (const float*)d_in[8];
    const float* w_fc   = (const float*)d_in[9];
    const float* b_fc   = (const float*)d_in[10];
    const float* w_proj = (const float*)d_in[11];
    const float* b_proj = (const float*)d_in[12];
    float* out = (float*)d_out;

    void *p_h, *p_qkv, *p_attn, *p_x1, *p_f;
    cudaGetSymbolAddress(&p_h, g_h);
    cudaGetSymbolAddress(&p_qkv, g_qkv);
    cudaGetSymbolAddress(&p_attn, g_attn);
    cudaGetSymbolAddress(&p_x1, g_x1);
    cudaGetSymbolAddress(&p_f, g_f);
    float* hbuf    = (float*)p_h;
    float* qkvbuf  = (float*)p_qkv;
    float* attnbuf = (float*)p_attn;
    float* x1buf   = (float*)p_x1;
    float* fbuf    = (float*)p_f;

    cudaFuncSetAttribute(attn_kernel, cudaFuncAttributeMaxDynamicSharedMemorySize,
                         ATTN_SMEM_BYTES);

    // 1) h = LN1(x)
    ln_kernel<<<ROWS, 256>>>(x, ln1_w, ln1_b, hbuf);
    // 2) qkv = h @ w_qkv^T + b_qkv
    gemm_kernel<0><<<dim3(3*EMB/128, ROWS/128), 256>>>(
        hbuf, w_qkv, b_qkv, nullptr, qkvbuf, ROWS, 3*EMB, EMB);
    // 3) attention
    attn_kernel<<<dim3(SEQ/64, BATCH*NHEAD), 256, ATTN_SMEM_BYTES>>>(qkvbuf, attnbuf);
    // 4) x1 = x + attn @ w_out^T + b_out
    gemm_kernel<1><<<dim3(EMB/128, ROWS/128), 256>>>(
        attnbuf, w_out, b_out, x, x1buf, ROWS, EMB, EMB);
    // 5) h = LN2(x1)
    ln_kernel<<<ROWS, 256>>>(x1buf, ln2_w, ln2_b, hbuf);
    // 6) f = QuickGELU(h @ w_fc^T + b_fc)
    gemm_kernel<2><<<dim3(4*EMB/128, ROWS/128), 256>>>(
        hbuf, w_fc, b_fc, nullptr, fbuf, ROWS, 4*EMB, EMB);
    // 7) out = x1 + f @ w_proj^T + b_proj
    gemm_kernel<1><<<dim3(EMB/128, ROWS/128), 256>>>(
        fbuf, w_proj, b_proj, x1buf, out, ROWS, EMB, 4*EMB);
}

// round 5
// speedup vs baseline: 1.8967x; 1.8967x over previous
#include <cuda_runtime.h>
#include <math.h>
#include <cstdint>

#define SEQ   2048
#define BATCH 4
#define EMB   768
#define NHEAD 12
#define DH    64
#define ROWS  (SEQ*BATCH)   // 8192

// ---------------- scratch (device globals; allocation-free) ----------------
__device__ float g_h[ROWS * EMB];          // LN output (tf32-rounded)
__device__ float g_qkv[ROWS * 3 * EMB];    // qkv (fp32)
__device__ float g_attn[ROWS * EMB];       // attention output (tf32-rounded)
__device__ float g_x1[ROWS * EMB];         // x + attn_out (fp32)
__device__ float g_f[ROWS * 4 * EMB];      // MLP hidden (tf32-rounded)
// tf32-rounded weight copies
__device__ float g_wq[3 * EMB * EMB];
__device__ float g_wo[EMB * EMB];
__device__ float g_wf[4 * EMB * EMB];
__device__ float g_wp[4 * EMB * EMB];

// ================= helpers =================
__device__ __forceinline__ uint32_t smem_u32(const void* p) {
    uint32_t a;
    asm("{ .reg .u64 t; cvta.to.shared.u64 t, %1; cvt.u32.u64 %0, t; }" : "=r"(a) : "l"(p));
    return a;
}
__device__ __forceinline__ float tf32r(float x) {
    uint32_t u;
    asm("cvt.rna.tf32.f32 %0, %1;" : "=r"(u) : "f"(x));
    return __uint_as_float(u);
}
#define CP_ASYNC16(dst, src) \
    asm volatile("cp.async.cg.shared.global [%0], [%1], 16;" :: "r"(dst), "l"(src) : "memory")
#define CP_COMMIT() asm volatile("cp.async.commit_group;" ::: "memory")
#define CP_WAIT1()  asm volatile("cp.async.wait_group 1;" ::: "memory")

__device__ __forceinline__ void ldmx4(uint32_t* r, uint32_t addr) {
    asm volatile("ldmatrix.sync.aligned.m8n8.x4.shared.b16 {%0,%1,%2,%3}, [%4];"
                 : "=r"(r[0]), "=r"(r[1]), "=r"(r[2]), "=r"(r[3]) : "r"(addr));
}
__device__ __forceinline__ void mma_tf32(float* c, const uint32_t* a, uint32_t b0, uint32_t b1) {
    asm volatile(
        "mma.sync.aligned.m16n8k8.row.col.f32.tf32.tf32.f32 "
        "{%0,%1,%2,%3}, {%4,%5,%6,%7}, {%8,%9}, {%0,%1,%2,%3};"
        : "+f"(c[0]), "+f"(c[1]), "+f"(c[2]), "+f"(c[3])
        : "r"(a[0]), "r"(a[1]), "r"(a[2]), "r"(a[3]), "r"(b0), "r"(b1));
}

// ---------------- weight tf32 rounding ----------------
__global__ void cvt_tf32_kernel(const float4* __restrict__ in, float4* __restrict__ out, int n4)
{
    int i = blockIdx.x * blockDim.x + threadIdx.x;
    int stride = gridDim.x * blockDim.x;
    for (; i < n4; i += stride) {
        float4 v = in[i];
        v.x = tf32r(v.x); v.y = tf32r(v.y); v.z = tf32r(v.z); v.w = tf32r(v.w);
        out[i] = v;
    }
}

// ---------------- LayerNorm (outputs tf32-rounded; feeds GEMM A only) -------
__inline__ __device__ float warp_sum(float v) {
    #pragma unroll
    for (int o = 16; o; o >>= 1) v += __shfl_xor_sync(0xffffffffu, v, o);
    return v;
}

__global__ void __launch_bounds__(256) ln_kernel(
    const float* __restrict__ x, const float* __restrict__ w,
    const float* __restrict__ b, float* __restrict__ y)
{
    __shared__ float rs[8], rq[8];
    __shared__ float s_mean, s_rstd;
    int row = blockIdx.x;
    int tid = threadIdx.x;
    const float* xr = x + (size_t)row * EMB;
    float v0 = xr[tid], v1 = xr[tid + 256], v2 = xr[tid + 512];
    float s = v0 + v1 + v2;
    float q = v0*v0 + v1*v1 + v2*v2;
    s = warp_sum(s); q = warp_sum(q);
    int wid = tid >> 5, lane = tid & 31;
    if (lane == 0) { rs[wid] = s; rq[wid] = q; }
    __syncthreads();
    if (tid == 0) {
        float S = 0.f, Q = 0.f;
        #pragma unroll
        for (int i = 0; i < 8; i++) { S += rs[i]; Q += rq[i]; }
        float mean = S * (1.0f / EMB);
        float var  = Q * (1.0f / EMB) - mean * mean;
        s_mean = mean;
        s_rstd = rsqrtf(var + 1e-5f);
    }
    __syncthreads();
    float mean = s_mean, rstd = s_rstd;
    float* yr = y + (size_t)row * EMB;
    yr[tid]       = tf32r((v0 - mean) * rstd * w[tid]       + b[tid]);
    yr[tid + 256] = tf32r((v1 - mean) * rstd * w[tid + 256] + b[tid + 256]);
    yr[tid + 512] = tf32r((v2 - mean) * rstd * w[tid + 512] + b[tid + 512]);
}

// ---------------- tf32 mma.sync GEMM: C[M,N] = A[M,K] @ B[N,K]^T + bias -----
// Tile 128x128, BK=32, 8 warps (2M x 4N), warp tile 64x32.
// smem rows padded to 36 floats (144B): ldmatrix + STS bank-conflict-free.
// MODE: 0 = bias, 1 = bias + residual, 2 = bias + QuickGELU (tf32-rounded out)
#define RPAD 36
#define TILE_F (128 * RPAD)                 // floats per matrix buffer
#define TCG_SMEM_BYTES (4 * TILE_F * 4)     // A0,A1,B0,B1 = 73728 B

template<int MODE>
__global__ void __launch_bounds__(256, 2) tc_gemm(
    const float* __restrict__ A, const float* __restrict__ B,
    const float* __restrict__ bias, const float* __restrict__ res,
    float* __restrict__ C, int M, int N, int K)
{
    extern __shared__ char smc[];
    uint32_t sbase = smem_u32(smc);
    // buffer offsets (bytes)
    const uint32_t offA[2] = { 0u, (uint32_t)(TILE_F * 4) };
    const uint32_t offB[2] = { (uint32_t)(2 * TILE_F * 4), (uint32_t)(3 * TILE_F * 4) };

    int tid = threadIdx.x;
    int wp = tid >> 5, lane = tid & 31;
    int wm = wp & 1, wn = wp >> 1;          // warp pos: 2 x 4

    int m0 = blockIdx.y * 128, n0 = blockIdx.x * 128;

    // staging map: 4 float4 per thread per matrix; f = tid + 256*i -> r=f>>3, c=f&7
    int rS[4], cS[4];
    #pragma unroll
    for (int i = 0; i < 4; i++) { int f = tid + 256 * i; rS[i] = f >> 3; cS[i] = f & 7; }

    const int NSTG = K >> 5;

    // stage 0
    {
        int k0 = 0;
        #pragma unroll
        for (int i = 0; i < 4; i++) {
            uint32_t da = sbase + offA[0] + (uint32_t)(rS[i] * RPAD + cS[i] * 4) * 4u;
            uint32_t db = sbase + offB[0] + (uint32_t)(rS[i] * RPAD + cS[i] * 4) * 4u;
            CP_ASYNC16(da, A + (size_t)(m0 + rS[i]) * K + k0 + cS[i] * 4);
            CP_ASYNC16(db, B + (size_t)(n0 + rS[i]) * K + k0 + cS[i] * 4);
        }
        CP_COMMIT();
    }

    float acc[4][4][4];
    #pragma unroll
    for (int mf = 0; mf < 4; mf++)
        #pragma unroll
        for (int nf = 0; nf < 4; nf++)
            #pragma unroll
            for (int r = 0; r < 4; r++) acc[mf][nf][r] = 0.f;

    // per-thread ldmatrix base offsets (bytes, within a buffer)
    uint32_t aoff = (uint32_t)(((wm * 64 + (lane & 15)) * RPAD + (lane >> 4) * 4) * 4);
    uint32_t boff = (uint32_t)(((wn * 32 + (lane & 15)) * RPAD + (lane >> 4) * 4) * 4);

    for (int it = 0; it < NSTG; it++) {
        int cur = it & 1;
        if (it + 1 < NSTG) {
            int k0 = (it + 1) << 5;
            int nb = (it + 1) & 1;
            #pragma unroll
            for (int i = 0; i < 4; i++) {
                uint32_t da = sbase + offA[nb] + (uint32_t)(rS[i] * RPAD + cS[i] * 4) * 4u;
                uint32_t db = sbase + offB[nb] + (uint32_t)(rS[i] * RPAD + cS[i] * 4) * 4u;
                CP_ASYNC16(da, A + (size_t)(m0 + rS[i]) * K + k0 + cS[i] * 4);
                CP_ASYNC16(db, B + (size_t)(n0 + rS[i]) * K + k0 + cS[i] * 4);
            }
        }
        CP_COMMIT();
        CP_WAIT1();
        __syncthreads();

        uint32_t ab = sbase + offA[cur] + aoff;
        uint32_t bb = sbase + offB[cur] + boff;
        #pragma unroll
        for (int ks = 0; ks < 4; ks++) {
            uint32_t afr[4][4];
            #pragma unroll
            for (int mf = 0; mf < 4; mf++)
                ldmx4(afr[mf], ab + (uint32_t)((mf * 16 * RPAD + ks * 8) * 4));
            uint32_t bfr0[4], bfr1[4];
            ldmx4(bfr0, bb + (uint32_t)((ks * 8) * 4));
            ldmx4(bfr1, bb + (uint32_t)((16 * RPAD + ks * 8) * 4));
            // b fragments: nf0=(bfr0[0],bfr0[2]) nf1=(bfr0[1],bfr0[3]) nf2=(bfr1[0],bfr1[2]) nf3=(bfr1[1],bfr1[3])
            #pragma unroll
            for (int mf = 0; mf < 4; mf++) {
                mma_tf32(acc[mf][0], afr[mf], bfr0[0], bfr0[2]);
                mma_tf32(acc[mf][1], afr[mf], bfr0[1], bfr0[3]);
                mma_tf32(acc[mf][2], afr[mf], bfr1[0], bfr1[2]);
                mma_tf32(acc[mf][3], afr[mf], bfr1[1], bfr1[3]);
            }
        }
        __syncthreads();
    }

    // epilogue
    int g = lane >> 2, q = lane & 3;
    #pragma unroll
    for (int mf = 0; mf < 4; mf++) {
        int r0 = m0 + wm * 64 + mf * 16 + g;
        #pragma unroll
        for (int nf = 0; nf < 4; nf++) {
            int col = n0 + wn * 32 + nf * 8 + 2 * q;
            float b0 = bias[col], b1 = bias[col + 1];
            float v0 = acc[mf][nf][0] + b0;
            float v1 = acc[mf][nf][1] + b1;
            float v2 = acc[mf][nf][2] + b0;
            float v3 = acc[mf][nf][3] + b1;
            if (MODE == 1) {
                const float* rp0 = res + (size_t)r0 * N + col;
                const float* rp1 = res + (size_t)(r0 + 8) * N + col;
                v0 += rp0[0]; v1 += rp0[1];
                v2 += rp1[0]; v3 += rp1[1];
            }
            if (MODE == 2) {
                v0 = tf32r(v0 / (1.0f + __expf(-1.702f * v0)));
                v1 = tf32r(v1 / (1.0f + __expf(-1.702f * v1)));
                v2 = tf32r(v2 / (1.0f + __expf(-1.702f * v2)));
                v3 = tf32r(v3 / (1.0f + __expf(-1.702f * v3)));
            }
            *(float2*)(C + (size_t)r0 * N + col)       = make_float2(v0, v1);
            *(float2*)(C + (size_t)(r0 + 8) * N + col) = make_float2(v2, v3);
        }
    }
}

// ---------------- Flash-style attention (fp32 SIMT) ----------------
#define ATTN_RED_STRIDE 17
#define ATTN_SMEM_FLOATS (4*64*64 + 64*ATTN_RED_STRIDE + 3*64)
#define ATTN_SMEM_BYTES  (ATTN_SMEM_FLOATS * 4)

__global__ void __launch_bounds__(256) attn_kernel(
    const float* __restrict__ qkv, float* __restrict__ out)
{
    extern __shared__ float smf[];
    float* Qs   = smf;
    float* Ks   = smf + 4096;
    float* Vs   = smf + 8192;
    float* Ss   = smf + 12288;
    float* red  = smf + 16384;
    float* mrow = smf + 16384 + 64*ATTN_RED_STRIDE;
    float* lrow = mrow + 64;
    float* frow = lrow + 64;

    int tid = threadIdx.x;
    int tx = tid & 15, ty = tid >> 4;
    int nh = blockIdx.y;
    int n = nh / NHEAD, h = nh % NHEAD;
    int q0 = blockIdx.x * 64;
    int qr = tid >> 2;
    int d4 = (tid & 3) * 16;

    {
        const float* qp = qkv + ((size_t)(q0 + qr) * BATCH + n) * (3*EMB) + h*DH + d4;
        #pragma unroll
        for (int i = 0; i < 4; i++) {
            float4 v = *(const float4*)(qp + i*4);
            Qs[(d4+i*4+0)*64 + qr] = v.x * 0.125f;
            Qs[(d4+i*4+1)*64 + qr] = v.y * 0.125f;
            Qs[(d4+i*4+2)*64 + qr] = v.z * 0.125f;
            Qs[(d4+i*4+3)*64 + qr] = v.w * 0.125f;
        }
    }
    if (tid < 64) { mrow[tid] = -1e30f; lrow[tid] = 0.f; }

    float o[4][4];
    #pragma unroll
    for (int i = 0; i < 4; i++)
        #pragma unroll
        for (int j = 0; j < 4; j++) o[i][j] = 0.f;

    for (int t0 = 0; t0 < SEQ; t0 += 64) {
        __syncthreads();
        {
            const float* kp = qkv + ((size_t)(t0 + qr) * BATCH + n) * (3*EMB) + EMB + h*DH + d4;
            const float* vp = kp + EMB;
            #pragma unroll
            for (int i = 0; i < 4; i++) {
                float4 kv4 = *(const float4*)(kp + i*4);
                Ks[(d4+i*4+0)*64 + qr] = kv4.x;
                Ks[(d4+i*4+1)*64 + qr] = kv4.y;
                Ks[(d4+i*4+2)*64 + qr] = kv4.z;
                Ks[(d4+i*4+3)*64 + qr] = kv4.w;
                float4 vv = *(const float4*)(vp + i*4);
                *(float4*)&Vs[qr*64 + d4 + i*4] = vv;
            }
        }
        __syncthreads();

        float s[4][4];
        #pragma unroll
        for (int i = 0; i < 4; i++)
            #pragma unroll
            for (int j = 0; j < 4; j++) s[i][j] = 0.f;
        #pragma unroll 16
        for (int d = 0; d < 64; d++) {
            float4 a  = *(const float4*)&Qs[d*64 + ty*4];
            float4 bq = *(const float4*)&Ks[d*64 + tx*4];
            float aa[4] = {a.x, a.y, a.z, a.w};
            float bb[4] = {bq.x, bq.y, bq.z, bq.w};
            #pragma unroll
            for (int i = 0; i < 4; i++)
                #pragma unroll
                for (int j = 0; j < 4; j++)
                    s[i][j] = fmaf(aa[i], bb[j], s[i][j]);
        }

        #pragma unroll
        for (int i = 0; i < 4; i++) {
            float lm = fmaxf(fmaxf(s[i][0], s[i][1]), fmaxf(s[i][2], s[i][3]));
            red[(ty*4+i)*ATTN_RED_STRIDE + tx] = lm;
        }
        __syncthreads();
        if (tid < 64) {
            float tm = red[tid*ATTN_RED_STRIDE];
            #pragma unroll
            for (int k2 = 1; k2 < 16; k2++) tm = fmaxf(tm, red[tid*ATTN_RED_STRIDE + k2]);
            float mo = mrow[tid], mn = fmaxf(mo, tm);
            frow[tid] = __expf(mo - mn);
            mrow[tid] = mn;
        }
        __syncthreads();

        #pragma unroll
        for (int i = 0; i < 4; i++) {
            float mn = mrow[ty*4+i];
            float p0 = __expf(s[i][0] - mn);
            float p1 = __expf(s[i][1] - mn);
            float p2 = __expf(s[i][2] - mn);
            float p3 = __expf(s[i][3] - mn);
            *(float4*)&Ss[(ty*4+i)*64 + tx*4] = make_float4(p0, p1, p2, p3);
            red[(ty*4+i)*ATTN_RED_STRIDE + tx] = p0 + p1 + p2 + p3;
        }
        __syncthreads();
        if (tid < 64) {
            float su = 0.f;
            #pragma unroll
            for (int k2 = 0; k2 < 16; k2++) su += red[tid*ATTN_RED_STRIDE + k2];
            lrow[tid] = lrow[tid] * frow[tid] + su;
        }

        float f0 = frow[ty*4+0], f1 = frow[ty*4+1], f2 = frow[ty*4+2], f3 = frow[ty*4+3];
        #pragma unroll
        for (int j = 0; j < 4; j++) {
            o[0][j] *= f0; o[1][j] *= f1; o[2][j] *= f2; o[3][j] *= f3;
        }
        #pragma unroll 16
        for (int kk = 0; kk < 64; kk++) {
            float4 bv = *(const float4*)&Vs[kk*64 + tx*4];
            float a0 = Ss[(ty*4+0)*64 + kk];
            float a1 = Ss[(ty*4+1)*64 + kk];
            float a2 = Ss[(ty*4+2)*64 + kk];
            float a3 = Ss[(ty*4+3)*64 + kk];
            o[0][0] = fmaf(a0, bv.x, o[0][0]); o[0][1] = fmaf(a0, bv.y, o[0][1]);
            o[0][2] = fmaf(a0, bv.z, o[0][2]); o[0][3] = fmaf(a0, bv.w, o[0][3]);
            o[1][0] = fmaf(a1, bv.x, o[1][0]); o[1][1] = fmaf(a1, bv.y, o[1][1]);
            o[1][2] = fmaf(a1, bv.z, o[1][2]); o[1][3] = fmaf(a1, bv.w, o[1][3]);
            o[2][0] = fmaf(a2, bv.x, o[2][0]); o[2][1] = fmaf(a2, bv.y, o[2][1]);
            o[2][2] = fmaf(a2, bv.z, o[2][2]); o[2][3] = fmaf(a2, bv.w, o[2][3]);
            o[3][0] = fmaf(a3, bv.x, o[3][0]); o[3][1] = fmaf(a3, bv.y, o[3][1]);
            o[3][2] = fmaf(a3, bv.z, o[3][2]); o[3][3] = fmaf(a3, bv.w, o[3][3]);
        }
    }
    __syncthreads();

    #pragma unroll
    for (int i = 0; i < 4; i++) {
        float inv = 1.0f / lrow[ty*4+i];
        float* op = out + ((size_t)(q0 + ty*4 + i) * BATCH + n) * EMB + h*DH + tx*4;
        *(float4*)op = make_float4(tf32r(o[i][0]*inv), tf32r(o[i][1]*inv),
                                   tf32r(o[i][2]*inv), tf32r(o[i][3]*inv));
    }
}

// ---------------- launch ----------------
extern "C" void kernel_launch(void* const* d_in, const int* in_sizes, int n_in,
                              void* d_out, int out_size)
{
    const float* x      = (const float*)d_in[0];
    const float* ln1_w  = (const float*)d_in[1];
    const float* ln1_b  = (const float*)d_in[2];
    const float* w_qkv  = (const float*)d_in[3];
    const float* b_qkv  = (const float*)d_in[4];
    const float* w_out  = (const float*)d_in[5];
    const float* b_out  = (const float*)d_in[6];
    const float* ln2_w  = (const float*)d_in[7];
    const float* ln2_b  = (const float*)d_in[8];
    const float* w_fc   = (const float*)d_in[9];
    const float* b_fc   = (const float*)d_in[10];
    const float* w_proj = (const float*)d_in[11];
    const float* b_proj = (const float*)d_in[12];
    float* out = (float*)d_out;

    void *p_h, *p_qkv, *p_attn, *p_x1, *p_f, *p_wq, *p_wo, *p_wf, *p_wp;
    cudaGetSymbolAddress(&p_h, g_h);
    cudaGetSymbolAddress(&p_qkv, g_qkv);
    cudaGetSymbolAddress(&p_attn, g_attn);
    cudaGetSymbolAddress(&p_x1, g_x1);
    cudaGetSymbolAddress(&p_f, g_f);
    cudaGetSymbolAddress(&p_wq, g_wq);
    cudaGetSymbolAddress(&p_wo, g_wo);
    cudaGetSymbolAddress(&p_wf, g_wf);
    cudaGetSymbolAddress(&p_wp, g_wp);
    float* hbuf    = (float*)p_h;
    float* qkvbuf  = (float*)p_qkv;
    float* attnbuf = (float*)p_attn;
    float* x1buf   = (float*)p_x1;
    float* fbuf    = (float*)p_f;
    float* wq = (float*)p_wq;
    float* wo = (float*)p_wo;
    float* wf = (float*)p_wf;
    float* wpj = (float*)p_wp;

    cudaFuncSetAttribute(attn_kernel, cudaFuncAttributeMaxDynamicSharedMemorySize,
                         ATTN_SMEM_BYTES);
    cudaFuncSetAttribute(tc_gemm<0>, cudaFuncAttributeMaxDynamicSharedMemorySize, TCG_SMEM_BYTES);
    cudaFuncSetAttribute(tc_gemm<1>, cudaFuncAttributeMaxDynamicSharedMemorySize, TCG_SMEM_BYTES);
    cudaFuncSetAttribute(tc_gemm<2>, cudaFuncAttributeMaxDynamicSharedMemorySize, TCG_SMEM_BYTES);

    // 0) tf32-round the weights
    cvt_tf32_kernel<<<512, 256>>>((const float4*)w_qkv,  (float4*)wq,  3*EMB*EMB/4);
    cvt_tf32_kernel<<<512, 256>>>((const float4*)w_out,  (float4*)wo,  EMB*EMB/4);
    cvt_tf32_kernel<<<512, 256>>>((const float4*)w_fc,   (float4*)wf,  4*EMB*EMB/4);
    cvt_tf32_kernel<<<512, 256>>>((const float4*)w_proj, (float4*)wpj, 4*EMB*EMB/4);

    // 1) h = LN1(x)  (tf32-rounded)
    ln_kernel<<<ROWS, 256>>>(x, ln1_w, ln1_b, hbuf);
    // 2) qkv = h @ w_qkv^T + b_qkv
    tc_gemm<0><<<dim3(3*EMB/128, ROWS/128), 256, TCG_SMEM_BYTES>>>(
        hbuf, wq, b_qkv, nullptr, qkvbuf, ROWS, 3*EMB, EMB);
    // 3) attention (output tf32-rounded)
    attn_kernel<<<dim3(SEQ/64, BATCH*NHEAD), 256, ATTN_SMEM_BYTES>>>(qkvbuf, attnbuf);
    // 4) x1 = x + attn @ w_out^T + b_out
    tc_gemm<1><<<dim3(EMB/128, ROWS/128), 256, TCG_SMEM_BYTES>>>(
        attnbuf, wo, b_out, x, x1buf, ROWS, EMB, EMB);
    // 5) h = LN2(x1)  (tf32-rounded)
    ln_kernel<<<ROWS, 256>>>(x1buf, ln2_w, ln2_b, hbuf);
    // 6) f = QuickGELU(h @ w_fc^T + b_fc)  (tf32-rounded)
    tc_gemm<2><<<dim3(4*EMB/128, ROWS/128), 256, TCG_SMEM_BYTES>>>(
        hbuf, wf, b_fc, nullptr, fbuf, ROWS, 4*EMB, EMB);
    // 7) out = x1 + f @ w_proj^T + b_proj
    tc_gemm<1><<<dim3(EMB/128, ROWS/128), 256, TCG_SMEM_BYTES>>>(
        fbuf, wpj, b_proj, x1buf, out, ROWS, EMB, 4*EMB);
}

// round 6
// speedup vs baseline: 2.7021x; 1.4246x over previous
#include <cuda_runtime.h>
#include <math.h>
#include <cstdint>

#define SEQ   2048
#define BATCH 4
#define EMB   768
#define NHEAD 12
#define DH    64
#define ROWS  (SEQ*BATCH)   // 8192

// ---------------- scratch (device globals; allocation-free) ----------------
__device__ float g_h[ROWS * EMB];          // LN output (tf32-rounded)
__device__ float g_qkv[ROWS * 3 * EMB];    // qkv (fp32)
__device__ float g_attn[ROWS * EMB];       // attention output (tf32-rounded)
__device__ float g_x1[ROWS * EMB];         // x + attn_out (fp32)
__device__ float g_f[ROWS * 4 * EMB];      // MLP hidden (tf32-rounded)
// tf32-rounded weight copies
__device__ float g_wq[3 * EMB * EMB];
__device__ float g_wo[EMB * EMB];
__device__ float g_wf[4 * EMB * EMB];
__device__ float g_wp[4 * EMB * EMB];

// ================= helpers =================
__device__ __forceinline__ uint32_t smem_u32(const void* p) {
    uint32_t a;
    asm("{ .reg .u64 t; cvta.to.shared.u64 t, %1; cvt.u32.u64 %0, t; }" : "=r"(a) : "l"(p));
    return a;
}
__device__ __forceinline__ float tf32r(float x) {
    uint32_t u;
    asm("cvt.rna.tf32.f32 %0, %1;" : "=r"(u) : "f"(x));
    return __uint_as_float(u);
}
#define CP_ASYNC16(dst, src) \
    asm volatile("cp.async.cg.shared.global [%0], [%1], 16;" :: "r"(dst), "l"(src) : "memory")
#define CP_COMMIT() asm volatile("cp.async.commit_group;" ::: "memory")
#define CP_WAIT1()  asm volatile("cp.async.wait_group 1;" ::: "memory")

__device__ __forceinline__ void ldmx4(uint32_t* r, uint32_t addr) {
    asm volatile("ldmatrix.sync.aligned.m8n8.x4.shared.b16 {%0,%1,%2,%3}, [%4];"
                 : "=r"(r[0]), "=r"(r[1]), "=r"(r[2]), "=r"(r[3]) : "r"(addr));
}
__device__ __forceinline__ void mma_tf32(float* c, const uint32_t* a, uint32_t b0, uint32_t b1) {
    asm volatile(
        "mma.sync.aligned.m16n8k8.row.col.f32.tf32.tf32.f32 "
        "{%0,%1,%2,%3}, {%4,%5,%6,%7}, {%8,%9}, {%0,%1,%2,%3};"
        : "+f"(c[0]), "+f"(c[1]), "+f"(c[2]), "+f"(c[3])
        : "r"(a[0]), "r"(a[1]), "r"(a[2]), "r"(a[3]), "r"(b0), "r"(b1));
}

// ---------------- weight tf32 rounding ----------------
__global__ void cvt_tf32_kernel(const float4* __restrict__ in, float4* __restrict__ out, int n4)
{
    int i = blockIdx.x * blockDim.x + threadIdx.x;
    int stride = gridDim.x * blockDim.x;
    for (; i < n4; i += stride) {
        float4 v = in[i];
        v.x = tf32r(v.x); v.y = tf32r(v.y); v.z = tf32r(v.z); v.w = tf32r(v.w);
        out[i] = v;
    }
}

// ---------------- LayerNorm (outputs tf32-rounded; feeds GEMM A only) -------
__inline__ __device__ float warp_sum(float v) {
    #pragma unroll
    for (int o = 16; o; o >>= 1) v += __shfl_xor_sync(0xffffffffu, v, o);
    return v;
}

__global__ void __launch_bounds__(256) ln_kernel(
    const float* __restrict__ x, const float* __restrict__ w,
    const float* __restrict__ b, float* __restrict__ y)
{
    __shared__ float rs[8], rq[8];
    __shared__ float s_mean, s_rstd;
    int row = blockIdx.x;
    int tid = threadIdx.x;
    const float* xr = x + (size_t)row * EMB;
    float v0 = xr[tid], v1 = xr[tid + 256], v2 = xr[tid + 512];
    float s = v0 + v1 + v2;
    float q = v0*v0 + v1*v1 + v2*v2;
    s = warp_sum(s); q = warp_sum(q);
    int wid = tid >> 5, lane = tid & 31;
    if (lane == 0) { rs[wid] = s; rq[wid] = q; }
    __syncthreads();
    if (tid == 0) {
        float S = 0.f, Q = 0.f;
        #pragma unroll
        for (int i = 0; i < 8; i++) { S += rs[i]; Q += rq[i]; }
        float mean = S * (1.0f / EMB);
        float var  = Q * (1.0f / EMB) - mean * mean;
        s_mean = mean;
        s_rstd = rsqrtf(var + 1e-5f);
    }
    __syncthreads();
    float mean = s_mean, rstd = s_rstd;
    float* yr = y + (size_t)row * EMB;
    yr[tid]       = tf32r((v0 - mean) * rstd * w[tid]       + b[tid]);
    yr[tid + 256] = tf32r((v1 - mean) * rstd * w[tid + 256] + b[tid + 256]);
    yr[tid + 512] = tf32r((v2 - mean) * rstd * w[tid + 512] + b[tid + 512]);
}

// ---------------- tf32 mma.sync GEMM (unchanged from round 5) ----------------
#define RPAD 36
#define TILE_F (128 * RPAD)
#define TCG_SMEM_BYTES (4 * TILE_F * 4)

template<int MODE>
__global__ void __launch_bounds__(256, 2) tc_gemm(
    const float* __restrict__ A, const float* __restrict__ B,
    const float* __restrict__ bias, const float* __restrict__ res,
    float* __restrict__ C, int M, int N, int K)
{
    extern __shared__ char smc[];
    uint32_t sbase = smem_u32(smc);
    const uint32_t offA[2] = { 0u, (uint32_t)(TILE_F * 4) };
    const uint32_t offB[2] = { (uint32_t)(2 * TILE_F * 4), (uint32_t)(3 * TILE_F * 4) };

    int tid = threadIdx.x;
    int wp = tid >> 5, lane = tid & 31;
    int wm = wp & 1, wn = wp >> 1;

    int m0 = blockIdx.y * 128, n0 = blockIdx.x * 128;

    int rS[4], cS[4];
    #pragma unroll
    for (int i = 0; i < 4; i++) { int f = tid + 256 * i; rS[i] = f >> 3; cS[i] = f & 7; }

    const int NSTG = K >> 5;

    {
        int k0 = 0;
        #pragma unroll
        for (int i = 0; i < 4; i++) {
            uint32_t da = sbase + offA[0] + (uint32_t)(rS[i] * RPAD + cS[i] * 4) * 4u;
            uint32_t db = sbase + offB[0] + (uint32_t)(rS[i] * RPAD + cS[i] * 4) * 4u;
            CP_ASYNC16(da, A + (size_t)(m0 + rS[i]) * K + k0 + cS[i] * 4);
            CP_ASYNC16(db, B + (size_t)(n0 + rS[i]) * K + k0 + cS[i] * 4);
        }
        CP_COMMIT();
    }

    float acc[4][4][4];
    #pragma unroll
    for (int mf = 0; mf < 4; mf++)
        #pragma unroll
        for (int nf = 0; nf < 4; nf++)
            #pragma unroll
            for (int r = 0; r < 4; r++) acc[mf][nf][r] = 0.f;

    uint32_t aoff = (uint32_t)(((wm * 64 + (lane & 15)) * RPAD + (lane >> 4) * 4) * 4);
    uint32_t boff = (uint32_t)(((wn * 32 + (lane & 15)) * RPAD + (lane >> 4) * 4) * 4);

    for (int it = 0; it < NSTG; it++) {
        int cur = it & 1;
        if (it + 1 < NSTG) {
            int k0 = (it + 1) << 5;
            int nb = (it + 1) & 1;
            #pragma unroll
            for (int i = 0; i < 4; i++) {
                uint32_t da = sbase + offA[nb] + (uint32_t)(rS[i] * RPAD + cS[i] * 4) * 4u;
                uint32_t db = sbase + offB[nb] + (uint32_t)(rS[i] * RPAD + cS[i] * 4) * 4u;
                CP_ASYNC16(da, A + (size_t)(m0 + rS[i]) * K + k0 + cS[i] * 4);
                CP_ASYNC16(db, B + (size_t)(n0 + rS[i]) * K + k0 + cS[i] * 4);
            }
        }
        CP_COMMIT();
        CP_WAIT1();
        __syncthreads();

        uint32_t ab = sbase + offA[cur] + aoff;
        uint32_t bb = sbase + offB[cur] + boff;
        #pragma unroll
        for (int ks = 0; ks < 4; ks++) {
            uint32_t afr[4][4];
            #pragma unroll
            for (int mf = 0; mf < 4; mf++)
                ldmx4(afr[mf], ab + (uint32_t)((mf * 16 * RPAD + ks * 8) * 4));
            uint32_t bfr0[4], bfr1[4];
            ldmx4(bfr0, bb + (uint32_t)((ks * 8) * 4));
            ldmx4(bfr1, bb + (uint32_t)((16 * RPAD + ks * 8) * 4));
            #pragma unroll
            for (int mf = 0; mf < 4; mf++) {
                mma_tf32(acc[mf][0], afr[mf], bfr0[0], bfr0[2]);
                mma_tf32(acc[mf][1], afr[mf], bfr0[1], bfr0[3]);
                mma_tf32(acc[mf][2], afr[mf], bfr1[0], bfr1[2]);
                mma_tf32(acc[mf][3], afr[mf], bfr1[1], bfr1[3]);
            }
        }
        __syncthreads();
    }

    int g = lane >> 2, q = lane & 3;
    #pragma unroll
    for (int mf = 0; mf < 4; mf++) {
        int r0 = m0 + wm * 64 + mf * 16 + g;
        #pragma unroll
        for (int nf = 0; nf < 4; nf++) {
            int col = n0 + wn * 32 + nf * 8 + 2 * q;
            float b0 = bias[col], b1 = bias[col + 1];
            float v0 = acc[mf][nf][0] + b0;
            float v1 = acc[mf][nf][1] + b1;
            float v2 = acc[mf][nf][2] + b0;
            float v3 = acc[mf][nf][3] + b1;
            if (MODE == 1) {
                const float* rp0 = res + (size_t)r0 * N + col;
                const float* rp1 = res + (size_t)(r0 + 8) * N + col;
                v0 += rp0[0]; v1 += rp0[1];
                v2 += rp1[0]; v3 += rp1[1];
            }
            if (MODE == 2) {
                v0 = tf32r(v0 / (1.0f + __expf(-1.702f * v0)));
                v1 = tf32r(v1 / (1.0f + __expf(-1.702f * v1)));
                v2 = tf32r(v2 / (1.0f + __expf(-1.702f * v2)));
                v3 = tf32r(v3 / (1.0f + __expf(-1.702f * v3)));
            }
            *(float2*)(C + (size_t)r0 * N + col)       = make_float2(v0, v1);
            *(float2*)(C + (size_t)(r0 + 8) * N + col) = make_float2(v2, v3);
        }
    }
}

// ---------------- tf32 mma.sync flash attention ----------------
// grid (SEQ/64, BATCH*NHEAD), 128 threads (4 warps). Warp w owns q-rows [w*16, w*16+16).
// smem: Qs[64][68], Ks[64][68], Vt[64][68] (V transposed), Ps[64][68] (warp-private rows).
#define AST 68
#define ATTN_SMEM_BYTES (4 * 64 * AST * 4)   // 69632

__global__ void __launch_bounds__(128) attn_kernel(
    const float* __restrict__ qkv, float* __restrict__ out)
{
    extern __shared__ float smf[];
    float* Qs = smf;
    float* Ks = smf + 64 * AST;
    float* Vt = smf + 2 * 64 * AST;
    float* Ps = smf + 3 * 64 * AST;

    int tid = threadIdx.x;
    int w = tid >> 5, lane = tid & 31;
    int g = lane >> 2, qd = lane & 3;
    int nh = blockIdx.y;
    int n = nh / NHEAD, h = nh % NHEAD;
    int q0 = blockIdx.x * 64;

    int lrow = tid >> 1;           // 0..63
    int lhalf = (tid & 1) * 32;    // 0 or 32

    // load Q tile (scaled by 1/8, tf32-rounded)
    {
        const float* qp = qkv + ((size_t)(q0 + lrow) * BATCH + n) * (3*EMB) + h*DH + lhalf;
        #pragma unroll
        for (int i = 0; i < 8; i++) {
            float4 v = *(const float4*)(qp + i * 4);
            Qs[lrow*AST + lhalf + i*4 + 0] = tf32r(v.x * 0.125f);
            Qs[lrow*AST + lhalf + i*4 + 1] = tf32r(v.y * 0.125f);
            Qs[lrow*AST + lhalf + i*4 + 2] = tf32r(v.z * 0.125f);
            Qs[lrow*AST + lhalf + i*4 + 3] = tf32r(v.w * 0.125f);
        }
    }

    float m0r = -1e30f, m1r = -1e30f, l0r = 0.f, l1r = 0.f;
    float o[8][4];
    #pragma unroll
    for (int i = 0; i < 8; i++)
        #pragma unroll
        for (int j = 0; j < 4; j++) o[i][j] = 0.f;

    uint32_t sb = smem_u32(smf);
    const uint32_t frag_off = (uint32_t)(((lane & 15) * AST + (lane >> 4) * 4) * 4);
    const uint32_t a_q = sb + (uint32_t)(w * 16 * AST * 4) + frag_off;
    const uint32_t a_k = sb + (uint32_t)(64 * AST * 4) + frag_off;
    const uint32_t a_v = sb + (uint32_t)(2 * 64 * AST * 4) + frag_off;
    const uint32_t a_p = sb + (uint32_t)(3 * 64 * AST * 4) + (uint32_t)(w * 16 * AST * 4) + frag_off;
    const uint32_t JSTRIDE = (uint32_t)(16 * AST * 4);

    for (int t0 = 0; t0 < SEQ; t0 += 64) {
        __syncthreads();
        // load K (rounded) and V (transposed, rounded)
        {
            const float* kp = qkv + ((size_t)(t0 + lrow) * BATCH + n) * (3*EMB) + EMB + h*DH + lhalf;
            const float* vp = kp + EMB;
            #pragma unroll
            for (int i = 0; i < 8; i++) {
                float4 kv = *(const float4*)(kp + i * 4);
                Ks[lrow*AST + lhalf + i*4 + 0] = tf32r(kv.x);
                Ks[lrow*AST + lhalf + i*4 + 1] = tf32r(kv.y);
                Ks[lrow*AST + lhalf + i*4 + 2] = tf32r(kv.z);
                Ks[lrow*AST + lhalf + i*4 + 3] = tf32r(kv.w);
                float4 vv = *(const float4*)(vp + i * 4);
                Vt[(lhalf + i*4 + 0)*AST + lrow] = tf32r(vv.x);
                Vt[(lhalf + i*4 + 1)*AST + lrow] = tf32r(vv.y);
                Vt[(lhalf + i*4 + 2)*AST + lrow] = tf32r(vv.z);
                Vt[(lhalf + i*4 + 3)*AST + lrow] = tf32r(vv.w);
            }
        }
        __syncthreads();

        // S = Q @ K^T : warp computes 16q x 64k
        float s[8][4];
        #pragma unroll
        for (int i = 0; i < 8; i++)
            #pragma unroll
            for (int j = 0; j < 4; j++) s[i][j] = 0.f;
        #pragma unroll
        for (int ks = 0; ks < 8; ks++) {
            uint32_t af[4];
            ldmx4(af, a_q + (uint32_t)(ks * 32));
            #pragma unroll
            for (int j = 0; j < 4; j++) {
                uint32_t bf[4];
                ldmx4(bf, a_k + j * JSTRIDE + (uint32_t)(ks * 32));
                mma_tf32(s[2*j+0], af, bf[0], bf[2]);
                mma_tf32(s[2*j+1], af, bf[1], bf[3]);
            }
        }

        // online softmax (rows g and g+8 of warp tile; row spread over quad lanes)
        float rm0 = -1e30f, rm1 = -1e30f;
        #pragma unroll
        for (int nf = 0; nf < 8; nf++) {
            rm0 = fmaxf(rm0, fmaxf(s[nf][0], s[nf][1]));
            rm1 = fmaxf(rm1, fmaxf(s[nf][2], s[nf][3]));
        }
        rm0 = fmaxf(rm0, __shfl_xor_sync(0xffffffffu, rm0, 1));
        rm0 = fmaxf(rm0, __shfl_xor_sync(0xffffffffu, rm0, 2));
        rm1 = fmaxf(rm1, __shfl_xor_sync(0xffffffffu, rm1, 1));
        rm1 = fmaxf(rm1, __shfl_xor_sync(0xffffffffu, rm1, 2));
        float mn0 = fmaxf(m0r, rm0), mn1 = fmaxf(m1r, rm1);
        float f0 = __expf(m0r - mn0), f1 = __expf(m1r - mn1);
        m0r = mn0; m1r = mn1;

        float rs0 = 0.f, rs1 = 0.f;
        int pr0 = (w * 16 + g) * AST + 2 * qd;
        int pr1 = pr0 + 8 * AST;
        #pragma unroll
        for (int nf = 0; nf < 8; nf++) {
            float p0 = tf32r(__expf(s[nf][0] - mn0));
            float p1 = tf32r(__expf(s[nf][1] - mn0));
            float p2 = tf32r(__expf(s[nf][2] - mn1));
            float p3 = tf32r(__expf(s[nf][3] - mn1));
            rs0 += p0 + p1; rs1 += p2 + p3;
            *(float2*)&Ps[pr0 + nf * 8] = make_float2(p0, p1);
            *(float2*)&Ps[pr1 + nf * 8] = make_float2(p2, p3);
        }
        rs0 += __shfl_xor_sync(0xffffffffu, rs0, 1);
        rs0 += __shfl_xor_sync(0xffffffffu, rs0, 2);
        rs1 += __shfl_xor_sync(0xffffffffu, rs1, 1);
        rs1 += __shfl_xor_sync(0xffffffffu, rs1, 2);
        l0r = l0r * f0 + rs0;
        l1r = l1r * f1 + rs1;

        #pragma unroll
        for (int nf = 0; nf < 8; nf++) {
            o[nf][0] *= f0; o[nf][1] *= f0; o[nf][2] *= f1; o[nf][3] *= f1;
        }
        __syncwarp();

        // O += P @ V  (A = Ps rows (warp-private), B = Vt rows d)
        #pragma unroll
        for (int ks = 0; ks < 8; ks++) {
            uint32_t af[4];
            ldmx4(af, a_p + (uint32_t)(ks * 32));
            #pragma unroll
            for (int j = 0; j < 4; j++) {
                uint32_t bf[4];
                ldmx4(bf, a_v + j * JSTRIDE + (uint32_t)(ks * 32));
                mma_tf32(o[2*j+0], af, bf[0], bf[2]);
                mma_tf32(o[2*j+1], af, bf[1], bf[3]);
            }
        }
        __syncwarp();
    }

    // epilogue (tf32-rounded: feeds next GEMM A operand)
    float inv0 = 1.0f / l0r, inv1 = 1.0f / l1r;
    int row0 = q0 + w * 16 + g;
    #pragma unroll
    for (int nf = 0; nf < 8; nf++) {
        int col = nf * 8 + 2 * qd;
        float* op0 = out + ((size_t)row0 * BATCH + n) * EMB + h * DH + col;
        float* op1 = out + ((size_t)(row0 + 8) * BATCH + n) * EMB + h * DH + col;
        *(float2*)op0 = make_float2(tf32r(o[nf][0] * inv0), tf32r(o[nf][1] * inv0));
        *(float2*)op1 = make_float2(tf32r(o[nf][2] * inv1), tf32r(o[nf][3] * inv1));
    }
}

// ---------------- launch ----------------
extern "C" void kernel_launch(void* const* d_in, const int* in_sizes, int n_in,
                              void* d_out, int out_size)
{
    const float* x      = (const float*)d_in[0];
    const float* ln1_w  = (const float*)d_in[1];
    const float* ln1_b  = (const float*)d_in[2];
    const float* w_qkv  = (const float*)d_in[3];
    const float* b_qkv  = (const float*)d_in[4];
    const float* w_out  = (const float*)d_in[5];
    const float* b_out  = (const float*)d_in[6];
    const float* ln2_w  = (const float*)d_in[7];
    const float* ln2_b  = (const float*)d_in[8];
    const float* w_fc   = (const float*)d_in[9];
    const float* b_fc   = (const float*)d_in[10];
    const float* w_proj = (const float*)d_in[11];
    const float* b_proj = (const float*)d_in[12];
    float* out = (float*)d_out;

    void *p_h, *p_qkv, *p_attn, *p_x1, *p_f, *p_wq, *p_wo, *p_wf, *p_wp;
    cudaGetSymbolAddress(&p_h, g_h);
    cudaGetSymbolAddress(&p_qkv, g_qkv);
    cudaGetSymbolAddress(&p_attn, g_attn);
    cudaGetSymbolAddress(&p_x1, g_x1);
    cudaGetSymbolAddress(&p_f, g_f);
    cudaGetSymbolAddress(&p_wq, g_wq);
    cudaGetSymbolAddress(&p_wo, g_wo);
    cudaGetSymbolAddress(&p_wf, g_wf);
    cudaGetSymbolAddress(&p_wp, g_wp);
    float* hbuf    = (float*)p_h;
    float* qkvbuf  = (float*)p_qkv;
    float* attnbuf = (float*)p_attn;
    float* x1buf   = (float*)p_x1;
    float* fbuf    = (float*)p_f;
    float* wq  = (float*)p_wq;
    float* wo  = (float*)p_wo;
    float* wf  = (float*)p_wf;
    float* wpj = (float*)p_wp;

    cudaFuncSetAttribute(attn_kernel, cudaFuncAttributeMaxDynamicSharedMemorySize,
                         ATTN_SMEM_BYTES);
    cudaFuncSetAttribute(tc_gemm<0>, cudaFuncAttributeMaxDynamicSharedMemorySize, TCG_SMEM_BYTES);
    cudaFuncSetAttribute(tc_gemm<1>, cudaFuncAttributeMaxDynamicSharedMemorySize, TCG_SMEM_BYTES);
    cudaFuncSetAttribute(tc_gemm<2>, cudaFuncAttributeMaxDynamicSharedMemorySize, TCG_SMEM_BYTES);

    // 0) tf32-round the weights
    cvt_tf32_kernel<<<512, 256>>>((const float4*)w_qkv,  (float4*)wq,  3*EMB*EMB/4);
    cvt_tf32_kernel<<<512, 256>>>((const float4*)w_out,  (float4*)wo,  EMB*EMB/4);
    cvt_tf32_kernel<<<512, 256>>>((const float4*)w_fc,   (float4*)wf,  4*EMB*EMB/4);
    cvt_tf32_kernel<<<512, 256>>>((const float4*)w_proj, (float4*)wpj, 4*EMB*EMB/4);

    // 1) h = LN1(x)  (tf32-rounded)
    ln_kernel<<<ROWS, 256>>>(x, ln1_w, ln1_b, hbuf);
    // 2) qkv = h @ w_qkv^T + b_qkv
    tc_gemm<0><<<dim3(3*EMB/128, ROWS/128), 256, TCG_SMEM_BYTES>>>(
        hbuf, wq, b_qkv, nullptr, qkvbuf, ROWS, 3*EMB, EMB);
    // 3) attention (tensor-core flash; output tf32-rounded)
    attn_kernel<<<dim3(SEQ/64, BATCH*NHEAD), 128, ATTN_SMEM_BYTES>>>(qkvbuf, attnbuf);
    // 4) x1 = x + attn @ w_out^T + b_out
    tc_gemm<1><<<dim3(EMB/128, ROWS/128), 256, TCG_SMEM_BYTES>>>(
        attnbuf, wo, b_out, x, x1buf, ROWS, EMB, EMB);
    // 5) h = LN2(x1)  (tf32-rounded)
    ln_kernel<<<ROWS, 256>>>(x1buf, ln2_w, ln2_b, hbuf);
    // 6) f = QuickGELU(h @ w_fc^T + b_fc)  (tf32-rounded)
    tc_gemm<2><<<dim3(4*EMB/128, ROWS/128), 256, TCG_SMEM_BYTES>>>(
        hbuf, wf, b_fc, nullptr, fbuf, ROWS, 4*EMB, EMB);
    // 7) out = x1 + f @ w_proj^T + b_proj
    tc_gemm<1><<<dim3(EMB/128, ROWS/128), 256, TCG_SMEM_BYTES>>>(
        fbuf, wpj, b_proj, x1buf, out, ROWS, EMB, 4*EMB);
}

// round 8
// speedup vs baseline: 3.5100x; 1.2990x over previous
#include <cuda_runtime.h>
#include <cuda_fp16.h>
#include <math.h>
#include <cstdint>

#define SEQ   2048
#define BATCH 4
#define EMB   768
#define NHEAD 12
#define DH    64
#define ROWS  (SEQ*BATCH)   // 8192

// ---------------- scratch (device globals; allocation-free) ----------------
__device__ __align__(16) __half g_hb[ROWS * EMB];        // LN out (fp16)
__device__ float g_qkv[ROWS * 3 * EMB];                  // qkv (fp32)
__device__ __align__(16) __half g_attnb[ROWS * EMB];     // attn out (fp16)
__device__ float g_x1[ROWS * EMB];                       // x + attn_out (fp32)
__device__ __align__(16) __half g_fb[ROWS * 4 * EMB];    // MLP hidden (fp16)
// fp16 weight copies
__device__ __align__(16) __half g_wq[3 * EMB * EMB];
__device__ __align__(16) __half g_wo[EMB * EMB];
__device__ __align__(16) __half g_wf[4 * EMB * EMB];
__device__ __align__(16) __half g_wp[4 * EMB * EMB];

// ================= helpers =================
__device__ __forceinline__ uint32_t smem_u32(const void* p) {
    uint32_t a;
    asm("{ .reg .u64 t; cvta.to.shared.u64 t, %1; cvt.u32.u64 %0, t; }" : "=r"(a) : "l"(p));
    return a;
}
__device__ __forceinline__ float tf32r(float x) {
    uint32_t u;
    asm("cvt.rna.tf32.f32 %0, %1;" : "=r"(u) : "f"(x));
    return __uint_as_float(u);
}
#define CP_ASYNC16(dst, src) \
    asm volatile("cp.async.cg.shared.global [%0], [%1], 16;" :: "r"(dst), "l"(src) : "memory")
#define CP_COMMIT() asm volatile("cp.async.commit_group;" ::: "memory")
#define CP_WAITG(n) asm volatile("cp.async.wait_group %0;" :: "n"(n) : "memory")

__device__ __forceinline__ void ldmx4(uint32_t* r, uint32_t addr) {
    asm volatile("ldmatrix.sync.aligned.m8n8.x4.shared.b16 {%0,%1,%2,%3}, [%4];"
                 : "=r"(r[0]), "=r"(r[1]), "=r"(r[2]), "=r"(r[3]) : "r"(addr));
}
__device__ __forceinline__ void mma_tf32(float* c, const uint32_t* a, uint32_t b0, uint32_t b1) {
    asm volatile(
        "mma.sync.aligned.m16n8k8.row.col.f32.tf32.tf32.f32 "
        "{%0,%1,%2,%3}, {%4,%5,%6,%7}, {%8,%9}, {%0,%1,%2,%3};"
        : "+f"(c[0]), "+f"(c[1]), "+f"(c[2]), "+f"(c[3])
        : "r"(a[0]), "r"(a[1]), "r"(a[2]), "r"(a[3]), "r"(b0), "r"(b1));
}
__device__ __forceinline__ void mma_f16(float* c, const uint32_t* a, uint32_t b0, uint32_t b1) {
    asm volatile(
        "mma.sync.aligned.m16n8k16.row.col.f32.f16.f16.f32 "
        "{%0,%1,%2,%3}, {%4,%5,%6,%7}, {%8,%9}, {%0,%1,%2,%3};"
        : "+f"(c[0]), "+f"(c[1]), "+f"(c[2]), "+f"(c[3])
        : "r"(a[0]), "r"(a[1]), "r"(a[2]), "r"(a[3]), "r"(b0), "r"(b1));
}

// ---------------- weight fp32 -> fp16 ----------------
__global__ void cvt_f16_kernel(const float4* __restrict__ in,
                               __half2* __restrict__ out, int n4)
{
    int i = blockIdx.x * blockDim.x + threadIdx.x;
    int stride = gridDim.x * blockDim.x;
    for (; i < n4; i += stride) {
        float4 v = in[i];
        out[2*i]   = __floats2half2_rn(v.x, v.y);
        out[2*i+1] = __floats2half2_rn(v.z, v.w);
    }
}

// ---------------- LayerNorm (fp16 out; feeds GEMM A only) ----------------
__inline__ __device__ float warp_sum(float v) {
    #pragma unroll
    for (int o = 16; o; o >>= 1) v += __shfl_xor_sync(0xffffffffu, v, o);
    return v;
}

__global__ void __launch_bounds__(256) ln_kernel(
    const float* __restrict__ x, const float* __restrict__ w,
    const float* __restrict__ b, __half* __restrict__ y)
{
    __shared__ float rs[8], rq[8];
    __shared__ float s_mean, s_rstd;
    int row = blockIdx.x;
    int tid = threadIdx.x;
    const float* xr = x + (size_t)row * EMB;
    float v0 = xr[tid], v1 = xr[tid + 256], v2 = xr[tid + 512];
    float s = v0 + v1 + v2;
    float q = v0*v0 + v1*v1 + v2*v2;
    s = warp_sum(s); q = warp_sum(q);
    int wid = tid >> 5, lane = tid & 31;
    if (lane == 0) { rs[wid] = s; rq[wid] = q; }
    __syncthreads();
    if (tid == 0) {
        float S = 0.f, Q = 0.f;
        #pragma unroll
        for (int i = 0; i < 8; i++) { S += rs[i]; Q += rq[i]; }
        float mean = S * (1.0f / EMB);
        float var  = Q * (1.0f / EMB) - mean * mean;
        s_mean = mean;
        s_rstd = rsqrtf(var + 1e-5f);
    }
    __syncthreads();
    float mean = s_mean, rstd = s_rstd;
    __half* yr = y + (size_t)row * EMB;
    yr[tid]       = __float2half_rn((v0 - mean) * rstd * w[tid]       + b[tid]);
    yr[tid + 256] = __float2half_rn((v1 - mean) * rstd * w[tid + 256] + b[tid + 256]);
    yr[tid + 512] = __float2half_rn((v2 - mean) * rstd * w[tid + 512] + b[tid + 512]);
}

// ---------------- fp16 mma.sync GEMM: C[M,N] = A[M,K] @ B[N,K]^T + bias -----
// Tile 128x128, BK=64, 8 warps (2M x 4N), warp tile 64x32, 2-stage cp.async.
// smem rows: 64 fp16 (128B) in 144B stride.
// MODE: 0 = bias (fp32 out), 1 = bias + residual (fp32 out),
//       2 = bias + QuickGELU (fp16 out)
#define SB    144                       // smem row stride bytes
#define GBUF  (128 * SB)                // 18432 B per matrix per stage
#define TCG_SMEM_BYTES (4 * GBUF)       // 73728

template<int MODE, typename OutT>
__global__ void __launch_bounds__(256, 2) tc_gemm(
    const __half* __restrict__ A, const __half* __restrict__ B,
    const float* __restrict__ bias, const float* __restrict__ res,
    OutT* __restrict__ C, int M, int N, int K)
{
    extern __shared__ char smc[];
    uint32_t sbase = smem_u32(smc);
    const uint32_t offA[2] = { 0u, (uint32_t)GBUF };
    const uint32_t offB[2] = { (uint32_t)(2 * GBUF), (uint32_t)(3 * GBUF) };

    int tid = threadIdx.x;
    int wp = tid >> 5, lane = tid & 31;
    int wm = wp & 1, wn = wp >> 1;

    int m0 = blockIdx.y * 128, n0 = blockIdx.x * 128;

    // staging map: 4 chunks (16B) per thread per matrix
    int rS[4], cS[4];
    #pragma unroll
    for (int i = 0; i < 4; i++) { int f = tid + 256 * i; rS[i] = f >> 3; cS[i] = f & 7; }

    const int NSTG = K >> 6;

    // preload stage 0
    #pragma unroll
    for (int i = 0; i < 4; i++) {
        uint32_t so = (uint32_t)(rS[i] * SB + cS[i] * 16);
        CP_ASYNC16(sbase + offA[0] + so, A + (size_t)(m0 + rS[i]) * K + cS[i] * 8);
        CP_ASYNC16(sbase + offB[0] + so, B + (size_t)(n0 + rS[i]) * K + cS[i] * 8);
    }
    CP_COMMIT();

    float acc[4][4][4];
    #pragma unroll
    for (int mf = 0; mf < 4; mf++)
        #pragma unroll
        for (int nf = 0; nf < 4; nf++)
            #pragma unroll
            for (int r = 0; r < 4; r++) acc[mf][nf][r] = 0.f;

    uint32_t a_base = (uint32_t)((wm * 64 + (lane & 15)) * SB + (lane >> 4) * 16);
    uint32_t b_base = (uint32_t)((wn * 32 + (lane & 15)) * SB + (lane >> 4) * 16);

    for (int it = 0; it < NSTG; it++) {
        int cur = it & 1;
        __syncthreads();                     // all warps done with buffer (it+1)&1
        if (it + 1 < NSTG) {
            int k0 = (it + 1) << 6;
            int nb = (it + 1) & 1;
            #pragma unroll
            for (int i = 0; i < 4; i++) {
                uint32_t so = (uint32_t)(rS[i] * SB + cS[i] * 16);
                CP_ASYNC16(sbase + offA[nb] + so, A + (size_t)(m0 + rS[i]) * K + k0 + cS[i] * 8);
                CP_ASYNC16(sbase + offB[nb] + so, B + (size_t)(n0 + rS[i]) * K + k0 + cS[i] * 8);
            }
        }
        CP_COMMIT();
        CP_WAITG(1);                          // stage `it` ready
        __syncthreads();                      // visibility of stage `it` to all warps

        uint32_t ab = sbase + offA[cur] + a_base;
        uint32_t bb = sbase + offB[cur] + b_base;
        #pragma unroll
        for (int ks = 0; ks < 4; ks++) {      // 4 x k16 = 64
            uint32_t afr[4][4];
            #pragma unroll
            for (int mf = 0; mf < 4; mf++)
                ldmx4(afr[mf], ab + (uint32_t)(mf * 16 * SB + ks * 32));
            uint32_t b0f[4], b1f[4];
            ldmx4(b0f, bb + (uint32_t)(ks * 32));
            ldmx4(b1f, bb + (uint32_t)(16 * SB + ks * 32));
            #pragma unroll
            for (int mf = 0; mf < 4; mf++) {
                mma_f16(acc[mf][0], afr[mf], b0f[0], b0f[2]);
                mma_f16(acc[mf][1], afr[mf], b0f[1], b0f[3]);
                mma_f16(acc[mf][2], afr[mf], b1f[0], b1f[2]);
                mma_f16(acc[mf][3], afr[mf], b1f[1], b1f[3]);
            }
        }
    }

    // epilogue
    int g = lane >> 2, q = lane & 3;
    #pragma unroll
    for (int mf = 0; mf < 4; mf++) {
        int r0 = m0 + wm * 64 + mf * 16 + g;
        #pragma unroll
        for (int nf = 0; nf < 4; nf++) {
            int col = n0 + wn * 32 + nf * 8 + 2 * q;
            float b0 = bias[col], b1 = bias[col + 1];
            float v0 = acc[mf][nf][0] + b0;
            float v1 = acc[mf][nf][1] + b1;
            float v2 = acc[mf][nf][2] + b0;
            float v3 = acc[mf][nf][3] + b1;
            if (MODE == 1) {
                const float* rp0 = res + (size_t)r0 * N + col;
                const float* rp1 = res + (size_t)(r0 + 8) * N + col;
                v0 += rp0[0]; v1 += rp0[1];
                v2 += rp1[0]; v3 += rp1[1];
            }
            if (MODE == 2) {
                v0 = v0 / (1.0f + __expf(-1.702f * v0));
                v1 = v1 / (1.0f + __expf(-1.702f * v1));
                v2 = v2 / (1.0f + __expf(-1.702f * v2));
                v3 = v3 / (1.0f + __expf(-1.702f * v3));
            }
            if (MODE == 2) {
                *(__half2*)((__half*)C + (size_t)r0 * N + col) =
                    __floats2half2_rn(v0, v1);
                *(__half2*)((__half*)C + (size_t)(r0 + 8) * N + col) =
                    __floats2half2_rn(v2, v3);
            } else {
                *(float2*)((float*)C + (size_t)r0 * N + col)       = make_float2(v0, v1);
                *(float2*)((float*)C + (size_t)(r0 + 8) * N + col) = make_float2(v2, v3);
            }
        }
    }
}

// ---------------- tf32 mma.sync flash attention (fp16 out) ----------------
#define AST 68
#define ATTN_SMEM_BYTES (4 * 64 * AST * 4)   // 69632

__global__ void __launch_bounds__(128) attn_kernel(
    const float* __restrict__ qkv, __half* __restrict__ out)
{
    extern __shared__ float smf[];
    float* Qs = smf;
    float* Ks = smf + 64 * AST;
    float* Vt = smf + 2 * 64 * AST;
    float* Ps = smf + 3 * 64 * AST;

    int tid = threadIdx.x;
    int w = tid >> 5, lane = tid & 31;
    int g = lane >> 2, qd = lane & 3;
    int nh = blockIdx.y;
    int n = nh / NHEAD, h = nh % NHEAD;
    int q0 = blockIdx.x * 64;

    int lrow = tid >> 1;
    int lhalf = (tid & 1) * 32;

    {
        const float* qp = qkv + ((size_t)(q0 + lrow) * BATCH + n) * (3*EMB) + h*DH + lhalf;
        #pragma unroll
        for (int i = 0; i < 8; i++) {
            float4 v = *(const float4*)(qp + i * 4);
            Qs[lrow*AST + lhalf + i*4 + 0] = tf32r(v.x * 0.125f);
            Qs[lrow*AST + lhalf + i*4 + 1] = tf32r(v.y * 0.125f);
            Qs[lrow*AST + lhalf + i*4 + 2] = tf32r(v.z * 0.125f);
            Qs[lrow*AST + lhalf + i*4 + 3] = tf32r(v.w * 0.125f);
        }
    }

    float m0r = -1e30f, m1r = -1e30f, l0r = 0.f, l1r = 0.f;
    float o[8][4];
    #pragma unroll
    for (int i = 0; i < 8; i++)
        #pragma unroll
        for (int j = 0; j < 4; j++) o[i][j] = 0.f;

    uint32_t sb = smem_u32(smf);
    const uint32_t frag_off = (uint32_t)(((lane & 15) * AST + (lane >> 4) * 4) * 4);
    const uint32_t a_q = sb + (uint32_t)(w * 16 * AST * 4) + frag_off;
    const uint32_t a_k = sb + (uint32_t)(64 * AST * 4) + frag_off;
    const uint32_t a_v = sb + (uint32_t)(2 * 64 * AST * 4) + frag_off;
    const uint32_t a_p = sb + (uint32_t)(3 * 64 * AST * 4) + (uint32_t)(w * 16 * AST * 4) + frag_off;
    const uint32_t JSTRIDE = (uint32_t)(16 * AST * 4);

    for (int t0 = 0; t0 < SEQ; t0 += 64) {
        __syncthreads();
        {
            const float* kp = qkv + ((size_t)(t0 + lrow) * BATCH + n) * (3*EMB) + EMB + h*DH + lhalf;
            const float* vp = kp + EMB;
            #pragma unroll
            for (int i = 0; i < 8; i++) {
                float4 kv = *(const float4*)(kp + i * 4);
                Ks[lrow*AST + lhalf + i*4 + 0] = tf32r(kv.x);
                Ks[lrow*AST + lhalf + i*4 + 1] = tf32r(kv.y);
                Ks[lrow*AST + lhalf + i*4 + 2] = tf32r(kv.z);
                Ks[lrow*AST + lhalf + i*4 + 3] = tf32r(kv.w);
                float4 vv = *(const float4*)(vp + i * 4);
                Vt[(lhalf + i*4 + 0)*AST + lrow] = tf32r(vv.x);
                Vt[(lhalf + i*4 + 1)*AST + lrow] = tf32r(vv.y);
                Vt[(lhalf + i*4 + 2)*AST + lrow] = tf32r(vv.z);
                Vt[(lhalf + i*4 + 3)*AST + lrow] = tf32r(vv.w);
            }
        }
        __syncthreads();

        float s[8][4];
        #pragma unroll
        for (int i = 0; i < 8; i++)
            #pragma unroll
            for (int j = 0; j < 4; j++) s[i][j] = 0.f;
        #pragma unroll
        for (int ks = 0; ks < 8; ks++) {
            uint32_t af[4];
            ldmx4(af, a_q + (uint32_t)(ks * 32));
            #pragma unroll
            for (int j = 0; j < 4; j++) {
                uint32_t bf[4];
                ldmx4(bf, a_k + j * JSTRIDE + (uint32_t)(ks * 32));
                mma_tf32(s[2*j+0], af, bf[0], bf[2]);
                mma_tf32(s[2*j+1], af, bf[1], bf[3]);
            }
        }

        float rm0 = -1e30f, rm1 = -1e30f;
        #pragma unroll
        for (int nf = 0; nf < 8; nf++) {
            rm0 = fmaxf(rm0, fmaxf(s[nf][0], s[nf][1]));
            rm1 = fmaxf(rm1, fmaxf(s[nf][2], s[nf][3]));
        }
        rm0 = fmaxf(rm0, __shfl_xor_sync(0xffffffffu, rm0, 1));
        rm0 = fmaxf(rm0, __shfl_xor_sync(0xffffffffu, rm0, 2));
        rm1 = fmaxf(rm1, __shfl_xor_sync(0xffffffffu, rm1, 1));
        rm1 = fmaxf(rm1, __shfl_xor_sync(0xffffffffu, rm1, 2));
        float mn0 = fmaxf(m0r, rm0), mn1 = fmaxf(m1r, rm1);
        float f0 = __expf(m0r - mn0), f1 = __expf(m1r - mn1);
        m0r = mn0; m1r = mn1;

        float rs0 = 0.f, rs1 = 0.f;
        int pr0 = (w * 16 + g) * AST + 2 * qd;
        int pr1 = pr0 + 8 * AST;
        #pragma unroll
        for (int nf = 0; nf < 8; nf++) {
            float p0 = tf32r(__expf(s[nf][0] - mn0));
            float p1 = tf32r(__expf(s[nf][1] - mn0));
            float p2 = tf32r(__expf(s[nf][2] - mn1));
            float p3 = tf32r(__expf(s[nf][3] - mn1));
            rs0 += p0 + p1; rs1 += p2 + p3;
            *(float2*)&Ps[pr0 + nf * 8] = make_float2(p0, p1);
            *(float2*)&Ps[pr1 + nf * 8] = make_float2(p2, p3);
        }
        rs0 += __shfl_xor_sync(0xffffffffu, rs0, 1);
        rs0 += __shfl_xor_sync(0xffffffffu, rs0, 2);
        rs1 += __shfl_xor_sync(0xffffffffu, rs1, 1);
        rs1 += __shfl_xor_sync(0xffffffffu, rs1, 2);
        l0r = l0r * f0 + rs0;
        l1r = l1r * f1 + rs1;

        #pragma unroll
        for (int nf = 0; nf < 8; nf++) {
            o[nf][0] *= f0; o[nf][1] *= f0; o[nf][2] *= f1; o[nf][3] *= f1;
        }
        __syncwarp();

        #pragma unroll
        for (int ks = 0; ks < 8; ks++) {
            uint32_t af[4];
            ldmx4(af, a_p + (uint32_t)(ks * 32));
            #pragma unroll
            for (int j = 0; j < 4; j++) {
                uint32_t bf[4];
                ldmx4(bf, a_v + j * JSTRIDE + (uint32_t)(ks * 32));
                mma_tf32(o[2*j+0], af, bf[0], bf[2]);
                mma_tf32(o[2*j+1], af, bf[1], bf[3]);
            }
        }
        __syncwarp();
    }

    float inv0 = 1.0f / l0r, inv1 = 1.0f / l1r;
    int row0 = q0 + w * 16 + g;
    #pragma unroll
    for (int nf = 0; nf < 8; nf++) {
        int col = nf * 8 + 2 * qd;
        __half* op0 = out + ((size_t)row0 * BATCH + n) * EMB + h * DH + col;
        __half* op1 = out + ((size_t)(row0 + 8) * BATCH + n) * EMB + h * DH + col;
        *(__half2*)op0 = __floats2half2_rn(o[nf][0] * inv0, o[nf][1] * inv0);
        *(__half2*)op1 = __floats2half2_rn(o[nf][2] * inv1, o[nf][3] * inv1);
    }
}

// ---------------- launch ----------------
extern "C" void kernel_launch(void* const* d_in, const int* in_sizes, int n_in,
                              void* d_out, int out_size)
{
    const float* x      = (const float*)d_in[0];
    const float* ln1_w  = (const float*)d_in[1];
    const float* ln1_b  = (const float*)d_in[2];
    const float* w_qkv  = (const float*)d_in[3];
    const float* b_qkv  = (const float*)d_in[4];
    const float* w_out  = (const float*)d_in[5];
    const float* b_out  = (const float*)d_in[6];
    const float* ln2_w  = (const float*)d_in[7];
    const float* ln2_b  = (const float*)d_in[8];
    const float* w_fc   = (const float*)d_in[9];
    const float* b_fc   = (const float*)d_in[10];
    const float* w_proj = (const float*)d_in[11];
    const float* b_proj = (const float*)d_in[12];
    float* out = (float*)d_out;

    void *p_hb, *p_qkv, *p_attnb, *p_x1, *p_fb, *p_wq, *p_wo, *p_wf, *p_wp;
    cudaGetSymbolAddress(&p_hb, g_hb);
    cudaGetSymbolAddress(&p_qkv, g_qkv);
    cudaGetSymbolAddress(&p_attnb, g_attnb);
    cudaGetSymbolAddress(&p_x1, g_x1);
    cudaGetSymbolAddress(&p_fb, g_fb);
    cudaGetSymbolAddress(&p_wq, g_wq);
    cudaGetSymbolAddress(&p_wo, g_wo);
    cudaGetSymbolAddress(&p_wf, g_wf);
    cudaGetSymbolAddress(&p_wp, g_wp);
    __half* hb    = (__half*)p_hb;
    float*  qkvb  = (float*)p_qkv;
    __half* attnb = (__half*)p_attnb;
    float*  x1b   = (float*)p_x1;
    __half* fb    = (__half*)p_fb;
    __half* wq  = (__half*)p_wq;
    __half* wo  = (__half*)p_wo;
    __half* wf  = (__half*)p_wf;
    __half* wpj = (__half*)p_wp;

    cudaFuncSetAttribute(attn_kernel, cudaFuncAttributeMaxDynamicSharedMemorySize,
                         ATTN_SMEM_BYTES);
    cudaFuncSetAttribute(tc_gemm<0, float>, cudaFuncAttributeMaxDynamicSharedMemorySize, TCG_SMEM_BYTES);
    cudaFuncSetAttribute(tc_gemm<1, float>, cudaFuncAttributeMaxDynamicSharedMemorySize, TCG_SMEM_BYTES);
    cudaFuncSetAttribute(tc_gemm<2, __half>, cudaFuncAttributeMaxDynamicSharedMemorySize, TCG_SMEM_BYTES);

    // 0) weights -> fp16
    cvt_f16_kernel<<<512, 256>>>((const float4*)w_qkv,  (__half2*)wq,  3*EMB*EMB/4);
    cvt_f16_kernel<<<512, 256>>>((const float4*)w_out,  (__half2*)wo,  EMB*EMB/4);
    cvt_f16_kernel<<<512, 256>>>((const float4*)w_fc,   (__half2*)wf,  4*EMB*EMB/4);
    cvt_f16_kernel<<<512, 256>>>((const float4*)w_proj, (__half2*)wpj, 4*EMB*EMB/4);

    // 1) h = LN1(x)  (fp16)
    ln_kernel<<<ROWS, 256>>>(x, ln1_w, ln1_b, hb);
    // 2) qkv = h @ w_qkv^T + b_qkv  (fp32 out)
    tc_gemm<0, float><<<dim3(3*EMB/128, ROWS/128), 256, TCG_SMEM_BYTES>>>(
        hb, wq, b_qkv, nullptr, qkvb, ROWS, 3*EMB, EMB);
    // 3) attention (tf32 flash; fp16 out)
    attn_kernel<<<dim3(SEQ/64, BATCH*NHEAD), 128, ATTN_SMEM_BYTES>>>(qkvb, attnb);
    // 4) x1 = x + attn @ w_out^T + b_out  (fp32 out)
    tc_gemm<1, float><<<dim3(EMB/128, ROWS/128), 256, TCG_SMEM_BYTES>>>(
        attnb, wo, b_out, x, x1b, ROWS, EMB, EMB);
    // 5) h = LN2(x1)  (fp16)
    ln_kernel<<<ROWS, 256>>>(x1b, ln2_w, ln2_b, hb);
    // 6) f = QuickGELU(h @ w_fc^T + b_fc)  (fp16 out)
    tc_gemm<2, __half><<<dim3(4*EMB/128, ROWS/128), 256, TCG_SMEM_BYTES>>>(
        hb, wf, b_fc, nullptr, fb, ROWS, 4*EMB, EMB);
    // 7) out = x1 + f @ w_proj^T + b_proj  (fp32 out)
    tc_gemm<1, float><<<dim3(EMB/128, ROWS/128), 256, TCG_SMEM_BYTES>>>(
        fb, wpj, b_proj, x1b, out, ROWS, EMB, 4*EMB);
}

// round 10
// speedup vs baseline: 6.5373x; 1.8625x over previous
#include <cuda_runtime.h>
#include <cuda_fp16.h>
#include <math.h>
#include <cstdint>

#define SEQ   2048
#define BATCH 4
#define EMB   768
#define NHEAD 12
#define DH    64
#define ROWS  (SEQ*BATCH)   // 8192

// ---------------- scratch (device globals; allocation-free) ----------------
__device__ __align__(16) __half g_hb[ROWS * EMB];        // LN out (fp16)
__device__ __align__(16) __half g_qkvh[ROWS * 3 * EMB];  // qkv (fp16)
__device__ __align__(16) __half g_attnb[ROWS * EMB];     // attn out (fp16)
__device__ float g_x1[ROWS * EMB];                       // x + attn_out (fp32)
__device__ __align__(16) __half g_fb[ROWS * 4 * EMB];    // MLP hidden (fp16)
// fp16 weight copies
__device__ __align__(16) __half g_wq[3 * EMB * EMB];
__device__ __align__(16) __half g_wo[EMB * EMB];
__device__ __align__(16) __half g_wf[4 * EMB * EMB];
__device__ __align__(16) __half g_wp[4 * EMB * EMB];

// ================= helpers =================
__device__ __forceinline__ uint32_t smem_u32(const void* p) {
    uint32_t a;
    asm("{ .reg .u64 t; cvta.to.shared.u64 t, %1; cvt.u32.u64 %0, t; }" : "=r"(a) : "l"(p));
    return a;
}
#define CP_ASYNC16(dst, src) \
    asm volatile("cp.async.cg.shared.global [%0], [%1], 16;" :: "r"(dst), "l"(src) : "memory")
#define CP_COMMIT() asm volatile("cp.async.commit_group;" ::: "memory")
#define CP_WAITG(n) asm volatile("cp.async.wait_group %0;" :: "n"(n) : "memory")

__device__ __forceinline__ void ldmx4(uint32_t* r, uint32_t addr) {
    asm volatile("ldmatrix.sync.aligned.m8n8.x4.shared.b16 {%0,%1,%2,%3}, [%4];"
                 : "=r"(r[0]), "=r"(r[1]), "=r"(r[2]), "=r"(r[3]) : "r"(addr));
}
__device__ __forceinline__ void ldmx4t(uint32_t* r, uint32_t addr) {
    asm volatile("ldmatrix.sync.aligned.m8n8.x4.trans.shared.b16 {%0,%1,%2,%3}, [%4];"
                 : "=r"(r[0]), "=r"(r[1]), "=r"(r[2]), "=r"(r[3]) : "r"(addr));
}
__device__ __forceinline__ void mma_f16(float* c, const uint32_t* a, uint32_t b0, uint32_t b1) {
    asm volatile(
        "mma.sync.aligned.m16n8k16.row.col.f32.f16.f16.f32 "
        "{%0,%1,%2,%3}, {%4,%5,%6,%7}, {%8,%9}, {%0,%1,%2,%3};"
        : "+f"(c[0]), "+f"(c[1]), "+f"(c[2]), "+f"(c[3])
        : "r"(a[0]), "r"(a[1]), "r"(a[2]), "r"(a[3]), "r"(b0), "r"(b1));
}
__device__ __forceinline__ uint32_t h2u(float a, float b) {
    __half2 h = __floats2half2_rn(a, b);
    return *reinterpret_cast<uint32_t*>(&h);
}

// ---------------- weight fp32 -> fp16 ----------------
__global__ void cvt_f16_kernel(const float4* __restrict__ in,
                               __half2* __restrict__ out, int n4)
{
    int i = blockIdx.x * blockDim.x + threadIdx.x;
    int stride = gridDim.x * blockDim.x;
    for (; i < n4; i += stride) {
        float4 v = in[i];
        out[2*i]   = __floats2half2_rn(v.x, v.y);
        out[2*i+1] = __floats2half2_rn(v.z, v.w);
    }
}

// ---------------- LayerNorm (fp16 out) ----------------
__inline__ __device__ float warp_sum(float v) {
    #pragma unroll
    for (int o = 16; o; o >>= 1) v += __shfl_xor_sync(0xffffffffu, v, o);
    return v;
}

__global__ void __launch_bounds__(256) ln_kernel(
    const float* __restrict__ x, const float* __restrict__ w,
    const float* __restrict__ b, __half* __restrict__ y)
{
    __shared__ float rs[8], rq[8];
    __shared__ float s_mean, s_rstd;
    int row = blockIdx.x;
    int tid = threadIdx.x;
    const float* xr = x + (size_t)row * EMB;
    float v0 = xr[tid], v1 = xr[tid + 256], v2 = xr[tid + 512];
    float s = v0 + v1 + v2;
    float q = v0*v0 + v1*v1 + v2*v2;
    s = warp_sum(s); q = warp_sum(q);
    int wid = tid >> 5, lane = tid & 31;
    if (lane == 0) { rs[wid] = s; rq[wid] = q; }
    __syncthreads();
    if (tid == 0) {
        float S = 0.f, Q = 0.f;
        #pragma unroll
        for (int i = 0; i < 8; i++) { S += rs[i]; Q += rq[i]; }
        float mean = S * (1.0f / EMB);
        float var  = Q * (1.0f / EMB) - mean * mean;
        s_mean = mean;
        s_rstd = rsqrtf(var + 1e-5f);
    }
    __syncthreads();
    float mean = s_mean, rstd = s_rstd;
    __half* yr = y + (size_t)row * EMB;
    yr[tid]       = __float2half_rn((v0 - mean) * rstd * w[tid]       + b[tid]);
    yr[tid + 256] = __float2half_rn((v1 - mean) * rstd * w[tid + 256] + b[tid + 256]);
    yr[tid + 512] = __float2half_rn((v2 - mean) * rstd * w[tid + 512] + b[tid + 512]);
}

// ---------------- fp16 mma.sync GEMM, 3-stage pipeline ----------------
// Tile 128x128, BK=64, 8 warps (2M x 4N), warp tile 64x32.
// smem rows: 64 fp16 (128B) in 144B stride. ONE __syncthreads per iteration.
// MODE: 0 = bias, 1 = bias + residual, 2 = bias + QuickGELU
#define SB    144
#define GBUF  (128 * SB)                 // 18432 B
#define TCG_SMEM_BYTES (6 * GBUF)        // 110592

template<int MODE, typename OutT>
__global__ void __launch_bounds__(256, 2) tc_gemm(
    const __half* __restrict__ A, const __half* __restrict__ B,
    const float* __restrict__ bias, const float* __restrict__ res,
    OutT* __restrict__ C, int M, int N, int K)
{
    extern __shared__ char smc[];
    uint32_t sbase = smem_u32(smc);

    int tid = threadIdx.x;
    int wp = tid >> 5, lane = tid & 31;
    int wm = wp & 1, wn = wp >> 1;

    int m0 = blockIdx.y * 128, n0 = blockIdx.x * 128;

    int rS[4], cS[4];
    #pragma unroll
    for (int i = 0; i < 4; i++) { int f = tid + 256 * i; rS[i] = f >> 3; cS[i] = f & 7; }

    const int NSTG = K >> 6;

    // preload stages 0,1
    #pragma unroll
    for (int st = 0; st < 2; st++) {
        int k0 = st << 6;
        #pragma unroll
        for (int i = 0; i < 4; i++) {
            uint32_t so = (uint32_t)(rS[i] * SB + cS[i] * 16);
            CP_ASYNC16(sbase + (uint32_t)(st * GBUF) + so,       A + (size_t)(m0 + rS[i]) * K + k0 + cS[i] * 8);
            CP_ASYNC16(sbase + (uint32_t)((3 + st) * GBUF) + so, B + (size_t)(n0 + rS[i]) * K + k0 + cS[i] * 8);
        }
        CP_COMMIT();
    }

    float acc[4][4][4];
    #pragma unroll
    for (int mf = 0; mf < 4; mf++)
        #pragma unroll
        for (int nf = 0; nf < 4; nf++)
            #pragma unroll
            for (int r = 0; r < 4; r++) acc[mf][nf][r] = 0.f;

    uint32_t a_base = (uint32_t)((wm * 64 + (lane & 15)) * SB + (lane >> 4) * 16);
    uint32_t b_base = (uint32_t)((wn * 32 + (lane & 15)) * SB + (lane >> 4) * 16);

    for (int it = 0; it < NSTG; it++) {
        CP_WAITG(1);                 // stage `it` landed
        __syncthreads();             // visible to all; all warps past stage (it+2)%3's prior use
        if (it + 2 < NSTG) {
            int st = (it + 2) % 3;
            int k0 = (it + 2) << 6;
            #pragma unroll
            for (int i = 0; i < 4; i++) {
                uint32_t so = (uint32_t)(rS[i] * SB + cS[i] * 16);
                CP_ASYNC16(sbase + (uint32_t)(st * GBUF) + so,       A + (size_t)(m0 + rS[i]) * K + k0 + cS[i] * 8);
                CP_ASYNC16(sbase + (uint32_t)((3 + st) * GBUF) + so, B + (size_t)(n0 + rS[i]) * K + k0 + cS[i] * 8);
            }
        }
        CP_COMMIT();

        int cur = it % 3;
        uint32_t ab = sbase + (uint32_t)(cur * GBUF) + a_base;
        uint32_t bb = sbase + (uint32_t)((3 + cur) * GBUF) + b_base;
        #pragma unroll
        for (int ks = 0; ks < 4; ks++) {
            uint32_t afr[4][4];
            #pragma unroll
            for (int mf = 0; mf < 4; mf++)
                ldmx4(afr[mf], ab + (uint32_t)(mf * 16 * SB + ks * 32));
            uint32_t b0f[4], b1f[4];
            ldmx4(b0f, bb + (uint32_t)(ks * 32));
            ldmx4(b1f, bb + (uint32_t)(16 * SB + ks * 32));
            #pragma unroll
            for (int mf = 0; mf < 4; mf++) {
                mma_f16(acc[mf][0], afr[mf], b0f[0], b0f[2]);
                mma_f16(acc[mf][1], afr[mf], b0f[1], b0f[3]);
                mma_f16(acc[mf][2], afr[mf], b1f[0], b1f[2]);
                mma_f16(acc[mf][3], afr[mf], b1f[1], b1f[3]);
            }
        }
    }

    // epilogue
    int g = lane >> 2, q = lane & 3;
    #pragma unroll
    for (int mf = 0; mf < 4; mf++) {
        int r0 = m0 + wm * 64 + mf * 16 + g;
        #pragma unroll
        for (int nf = 0; nf < 4; nf++) {
            int col = n0 + wn * 32 + nf * 8 + 2 * q;
            float b0 = bias[col], b1 = bias[col + 1];
            float v0 = acc[mf][nf][0] + b0;
            float v1 = acc[mf][nf][1] + b1;
            float v2 = acc[mf][nf][2] + b0;
            float v3 = acc[mf][nf][3] + b1;
            if (MODE == 1) {
                const float* rp0 = res + (size_t)r0 * N + col;
                const float* rp1 = res + (size_t)(r0 + 8) * N + col;
                v0 += rp0[0]; v1 += rp0[1];
                v2 += rp1[0]; v3 += rp1[1];
            }
            if (MODE == 2) {
                v0 = v0 / (1.0f + __expf(-1.702f * v0));
                v1 = v1 / (1.0f + __expf(-1.702f * v1));
                v2 = v2 / (1.0f + __expf(-1.702f * v2));
                v3 = v3 / (1.0f + __expf(-1.702f * v3));
            }
            if (sizeof(OutT) == 2) {
                *(__half2*)((__half*)C + (size_t)r0 * N + col)       = __floats2half2_rn(v0, v1);
                *(__half2*)((__half*)C + (size_t)(r0 + 8) * N + col) = __floats2half2_rn(v2, v3);
            } else {
                *(float2*)((float*)C + (size_t)r0 * N + col)       = make_float2(v0, v1);
                *(float2*)((float*)C + (size_t)(r0 + 8) * N + col) = make_float2(v2, v3);
            }
        }
    }
}

// ---------------- fp16 mma.sync flash attention ----------------
// grid (SEQ/64, BATCH*NHEAD), 128 threads (4 warps); warp w owns q-rows w*16..+16.
// P converts accumulator->A-fragments in registers (no smem round-trip).
// V consumed via ldmatrix.trans from K-major tile. K/V cp.async, 3-stage.
// smem fp16 tiles, 144B row stride: Q | K0 K1 K2 | V0 V1 V2
#define ATILE 9216                       // 64 rows * 144 B
#define ATTN_SMEM_BYTES (7 * ATILE)      // 64512

__global__ void __launch_bounds__(128) attn_kernel(
    const __half* __restrict__ qkv, __half* __restrict__ out)
{
    extern __shared__ char sma[];
    uint32_t sb = smem_u32(sma);

    int tid = threadIdx.x;
    int w = tid >> 5, lane = tid & 31;
    int g = lane >> 2, qd = lane & 3;
    int nh = blockIdx.y;
    int n = nh / NHEAD, h = nh % NHEAD;
    int q0 = blockIdx.x * 64;

    const size_t GROW = (size_t)BATCH * 3 * EMB;   // halves per seq step

    int rT[4], cT[4];
    #pragma unroll
    for (int i = 0; i < 4; i++) { int f = tid + 128 * i; rT[i] = f >> 3; cT[i] = f & 7; }

    const __half* qbase = qkv + ((size_t)q0 * BATCH + n) * (3 * EMB) + h * DH;
    const __half* kroot = qkv + (size_t)n * (3 * EMB) + EMB + h * DH;

    // preload: group0 = {Q, K0, V0}; group1 = {K1, V1}
    #pragma unroll
    for (int i = 0; i < 4; i++) {
        uint32_t so = (uint32_t)(rT[i] * SB + cT[i] * 16);
        CP_ASYNC16(sb + so, qbase + (size_t)rT[i] * GROW + cT[i] * 8);
    }
    #pragma unroll
    for (int st = 0; st < 2; st++) {
        const __half* kb = kroot + (size_t)(st * 64) * GROW;
        #pragma unroll
        for (int i = 0; i < 4; i++) {
            uint32_t so = (uint32_t)(rT[i] * SB + cT[i] * 16);
            const __half* src = kb + (size_t)rT[i] * GROW + cT[i] * 8;
            CP_ASYNC16(sb + (uint32_t)((1 + st) * ATILE) + so, src);
            CP_ASYNC16(sb + (uint32_t)((4 + st) * ATILE) + so, src + EMB);
        }
        CP_COMMIT();
    }

    float m0r = -1e30f, m1r = -1e30f, l0r = 0.f, l1r = 0.f;
    float o[8][4];
    #pragma unroll
    for (int i = 0; i < 8; i++)
        #pragma unroll
        for (int j = 0; j < 4; j++) o[i][j] = 0.f;

    const uint32_t frag = (uint32_t)((lane & 15) * SB + (lane >> 4) * 16);
    const uint32_t a_q = sb + (uint32_t)(w * 16 * SB) + frag;

    const int NT = SEQ / 64;
    for (int t = 0; t < NT; t++) {
        CP_WAITG(1);
        __syncthreads();
        if (t + 2 < NT) {
            int st = (t + 2) % 3;
            const __half* kb = kroot + (size_t)((t + 2) * 64) * GROW;
            #pragma unroll
            for (int i = 0; i < 4; i++) {
                uint32_t so = (uint32_t)(rT[i] * SB + cT[i] * 16);
                const __half* src = kb + (size_t)rT[i] * GROW + cT[i] * 8;
                CP_ASYNC16(sb + (uint32_t)((1 + st) * ATILE) + so, src);
                CP_ASYNC16(sb + (uint32_t)((4 + st) * ATILE) + so, src + EMB);
            }
        }
        CP_COMMIT();

        int cur = t % 3;
        uint32_t kbuf = sb + (uint32_t)((1 + cur) * ATILE);
        uint32_t vbuf = sb + (uint32_t)((4 + cur) * ATILE);

        // S = Q @ K^T  (16q x 64k per warp)
        float s4[8][4];
        #pragma unroll
        for (int i = 0; i < 8; i++)
            #pragma unroll
            for (int j = 0; j < 4; j++) s4[i][j] = 0.f;
        #pragma unroll
        for (int kd = 0; kd < 4; kd++) {
            uint32_t aq[4];
            ldmx4(aq, a_q + (uint32_t)(kd * 32));
            #pragma unroll
            for (int j = 0; j < 4; j++) {
                uint32_t bk[4];
                ldmx4(bk, kbuf + (uint32_t)(j * 16 * SB + kd * 32) + frag - (uint32_t)((lane & 15) * SB) + (uint32_t)((lane & 15) * SB));
                mma_f16(s4[2*j+0], aq, bk[0], bk[2]);
                mma_f16(s4[2*j+1], aq, bk[1], bk[3]);
            }
        }
        // fold softmax scale
        #pragma unroll
        for (int i = 0; i < 8; i++)
            #pragma unroll
            for (int j = 0; j < 4; j++) s4[i][j] *= 0.125f;

        // online softmax: rows g (c0,c1) and g+8 (c2,c3), spread over quad lanes
        float rm0 = -1e30f, rm1 = -1e30f;
        #pragma unroll
        for (int i = 0; i < 8; i++) {
            rm0 = fmaxf(rm0, fmaxf(s4[i][0], s4[i][1]));
            rm1 = fmaxf(rm1, fmaxf(s4[i][2], s4[i][3]));
        }
        rm0 = fmaxf(rm0, __shfl_xor_sync(0xffffffffu, rm0, 1));
        rm0 = fmaxf(rm0, __shfl_xor_sync(0xffffffffu, rm0, 2));
        rm1 = fmaxf(rm1, __shfl_xor_sync(0xffffffffu, rm1, 1));
        rm1 = fmaxf(rm1, __shfl_xor_sync(0xffffffffu, rm1, 2));
        float mn0 = fmaxf(m0r, rm0), mn1 = fmaxf(m1r, rm1);
        float f0 = __expf(m0r - mn0), f1 = __expf(m1r - mn1);
        m0r = mn0; m1r = mn1;

        // P = exp(S - m); convert to A-fragments in registers
        uint32_t pa[4][4];
        float rs0 = 0.f, rs1 = 0.f;
        #pragma unroll
        for (int j = 0; j < 4; j++) {
            float pa0 = __expf(s4[2*j+0][0] - mn0), pa1 = __expf(s4[2*j+0][1] - mn0);
            float pa2 = __expf(s4[2*j+0][2] - mn1), pa3 = __expf(s4[2*j+0][3] - mn1);
            float pb0 = __expf(s4[2*j+1][0] - mn0), pb1 = __expf(s4[2*j+1][1] - mn0);
            float pb2 = __expf(s4[2*j+1][2] - mn1), pb3 = __expf(s4[2*j+1][3] - mn1);
            rs0 += pa0 + pa1 + pb0 + pb1;
            rs1 += pa2 + pa3 + pb2 + pb3;
            pa[j][0] = h2u(pa0, pa1);   // (g,   k-lo)
            pa[j][1] = h2u(pa2, pa3);   // (g+8, k-lo)
            pa[j][2] = h2u(pb0, pb1);   // (g,   k-hi)
            pa[j][3] = h2u(pb2, pb3);   // (g+8, k-hi)
        }
        rs0 += __shfl_xor_sync(0xffffffffu, rs0, 1);
        rs0 += __shfl_xor_sync(0xffffffffu, rs0, 2);
        rs1 += __shfl_xor_sync(0xffffffffu, rs1, 1);
        rs1 += __shfl_xor_sync(0xffffffffu, rs1, 2);
        l0r = l0r * f0 + rs0;
        l1r = l1r * f1 + rs1;

        // rescale O
        #pragma unroll
        for (int i = 0; i < 8; i++) {
            o[i][0] *= f0; o[i][1] *= f0; o[i][2] *= f1; o[i][3] *= f1;
        }

        // O += P @ V : B via ldmatrix.trans of V[key][d]
        #pragma unroll
        for (int ks = 0; ks < 4; ks++) {
            #pragma unroll
            for (int t4 = 0; t4 < 4; t4++) {
                uint32_t bv[4];
                ldmx4t(bv, vbuf + (uint32_t)(ks * 16 * SB + t4 * 32) + frag);
                mma_f16(o[2*t4+0], pa[ks], bv[0], bv[1]);
                mma_f16(o[2*t4+1], pa[ks], bv[2], bv[3]);
            }
        }
    }

    // epilogue (fp16 out)
    float inv0 = 1.0f / l0r, inv1 = 1.0f / l1r;
    int row0 = q0 + w * 16 + g;
    #pragma unroll
    for (int jj = 0; jj < 8; jj++) {
        int col = jj * 8 + 2 * qd;
        __half* op0 = out + ((size_t)row0 * BATCH + n) * EMB + h * DH + col;
        __half* op1 = out + ((size_t)(row0 + 8) * BATCH + n) * EMB + h * DH + col;
        *(__half2*)op0 = __floats2half2_rn(o[jj][0] * inv0, o[jj][1] * inv0);
        *(__half2*)op1 = __floats2half2_rn(o[jj][2] * inv1, o[jj][3] * inv1);
    }
}

// ---------------- launch ----------------
extern "C" void kernel_launch(void* const* d_in, const int* in_sizes, int n_in,
                              void* d_out, int out_size)
{
    const float* x      = (const float*)d_in[0];
    const float* ln1_w  = (const float*)d_in[1];
    const float* ln1_b  = (const float*)d_in[2];
    const float* w_qkv  = (const float*)d_in[3];
    const float* b_qkv  = (const float*)d_in[4];
    const float* w_out  = (const float*)d_in[5];
    const float* b_out  = (const float*)d_in[6];
    const float* ln2_w  = (const float*)d_in[7];
    const float* ln2_b  = (const float*)d_in[8];
    const float* w_fc   = (const float*)d_in[9];
    const float* b_fc   = (const float*)d_in[10];
    const float* w_proj = (const float*)d_in[11];
    const float* b_proj = (const float*)d_in[12];
    float* out = (float*)d_out;

    void *p_hb, *p_qkvh, *p_attnb, *p_x1, *p_fb, *p_wq, *p_wo, *p_wf, *p_wp;
    cudaGetSymbolAddress(&p_hb, g_hb);
    cudaGetSymbolAddress(&p_qkvh, g_qkvh);
    cudaGetSymbolAddress(&p_attnb, g_attnb);
    cudaGetSymbolAddress(&p_x1, g_x1);
    cudaGetSymbolAddress(&p_fb, g_fb);
    cudaGetSymbolAddress(&p_wq, g_wq);
    cudaGetSymbolAddress(&p_wo, g_wo);
    cudaGetSymbolAddress(&p_wf, g_wf);
    cudaGetSymbolAddress(&p_wp, g_wp);
    __half* hb    = (__half*)p_hb;
    __half* qkvh  = (__half*)p_qkvh;
    __half* attnb = (__half*)p_attnb;
    float*  x1b   = (float*)p_x1;
    __half* fb    = (__half*)p_fb;
    __half* wq  = (__half*)p_wq;
    __half* wo  = (__half*)p_wo;
    __half* wf  = (__half*)p_wf;
    __half* wpj = (__half*)p_wp;

    cudaFuncSetAttribute(attn_kernel, cudaFuncAttributeMaxDynamicSharedMemorySize,
                         ATTN_SMEM_BYTES);
    cudaFuncSetAttribute(tc_gemm<0, __half>, cudaFuncAttributeMaxDynamicSharedMemorySize, TCG_SMEM_BYTES);
    cudaFuncSetAttribute(tc_gemm<1, float>, cudaFuncAttributeMaxDynamicSharedMemorySize, TCG_SMEM_BYTES);
    cudaFuncSetAttribute(tc_gemm<2, __half>, cudaFuncAttributeMaxDynamicSharedMemorySize, TCG_SMEM_BYTES);

    // 0) weights -> fp16
    cvt_f16_kernel<<<512, 256>>>((const float4*)w_qkv,  (__half2*)wq,  3*EMB*EMB/4);
    cvt_f16_kernel<<<512, 256>>>((const float4*)w_out,  (__half2*)wo,  EMB*EMB/4);
    cvt_f16_kernel<<<512, 256>>>((const float4*)w_fc,   (__half2*)wf,  4*EMB*EMB/4);
    cvt_f16_kernel<<<512, 256>>>((const float4*)w_proj, (__half2*)wpj, 4*EMB*EMB/4);

    // 1) h = LN1(x)  (fp16)
    ln_kernel<<<ROWS, 256>>>(x, ln1_w, ln1_b, hb);
    // 2) qkv = h @ w_qkv^T + b_qkv  (fp16 out)
    tc_gemm<0, __half><<<dim3(3*EMB/128, ROWS/128), 256, TCG_SMEM_BYTES>>>(
        hb, wq, b_qkv, nullptr, qkvh, ROWS, 3*EMB, EMB);
    // 3) attention (fp16 flash; fp16 out)
    attn_kernel<<<dim3(SEQ/64, BATCH*NHEAD), 128, ATTN_SMEM_BYTES>>>(qkvh, attnb);
    // 4) x1 = x + attn @ w_out^T + b_out  (fp32 out)
    tc_gemm<1, float><<<dim3(EMB/128, ROWS/128), 256, TCG_SMEM_BYTES>>>(
        attnb, wo, b_out, x, x1b, ROWS, EMB, EMB);
    // 5) h = LN2(x1)  (fp16)
    ln_kernel<<<ROWS, 256>>>(x1b, ln2_w, ln2_b, hb);
    // 6) f = QuickGELU(h @ w_fc^T + b_fc)  (fp16 out)
    tc_gemm<2, __half><<<dim3(4*EMB/128, ROWS/128), 256, TCG_SMEM_BYTES>>>(
        hb, wf, b_fc, nullptr, fb, ROWS, 4*EMB, EMB);
    // 7) out = x1 + f @ w_proj^T + b_proj  (fp32 out)
    tc_gemm<1, float><<<dim3(EMB/128, ROWS/128), 256, TCG_SMEM_BYTES>>>(
        fb, wpj, b_proj, x1b, out, ROWS, EMB, 4*EMB);
}

// round 11
// speedup vs baseline: 6.7205x; 1.0280x over previous
#include <cuda_runtime.h>
#include <cuda_fp16.h>
#include <math.h>
#include <cstdint>

#define SEQ   2048
#define BATCH 4
#define EMB   768
#define NHEAD 12
#define DH    64
#define ROWS  (SEQ*BATCH)   // 8192

// ---------------- scratch (device globals; allocation-free) ----------------
__device__ __align__(16) __half g_hb[ROWS * EMB];        // LN out (fp16)
__device__ __align__(16) __half g_qkvh[ROWS * 3 * EMB];  // qkv (fp16)
__device__ __align__(16) __half g_attnb[ROWS * EMB];     // attn out (fp16)
__device__ float g_x1[ROWS * EMB];                       // x + attn_out (fp32)
__device__ __align__(16) __half g_fb[ROWS * 4 * EMB];    // MLP hidden (fp16)
// fp16 weight copies
__device__ __align__(16) __half g_wq[3 * EMB * EMB];
__device__ __align__(16) __half g_wo[EMB * EMB];
__device__ __align__(16) __half g_wf[4 * EMB * EMB];
__device__ __align__(16) __half g_wp[4 * EMB * EMB];

// ================= helpers =================
__device__ __forceinline__ uint32_t smem_u32(const void* p) {
    uint32_t a;
    asm("{ .reg .u64 t; cvta.to.shared.u64 t, %1; cvt.u32.u64 %0, t; }" : "=r"(a) : "l"(p));
    return a;
}
#define CP_ASYNC16(dst, src) \
    asm volatile("cp.async.cg.shared.global [%0], [%1], 16;" :: "r"(dst), "l"(src) : "memory")
#define CP_COMMIT() asm volatile("cp.async.commit_group;" ::: "memory")
#define CP_WAITG(n) asm volatile("cp.async.wait_group %0;" :: "n"(n) : "memory")

__device__ __forceinline__ void ldmx4(uint32_t* r, uint32_t addr) {
    asm volatile("ldmatrix.sync.aligned.m8n8.x4.shared.b16 {%0,%1,%2,%3}, [%4];"
                 : "=r"(r[0]), "=r"(r[1]), "=r"(r[2]), "=r"(r[3]) : "r"(addr));
}
__device__ __forceinline__ void ldmx4t(uint32_t* r, uint32_t addr) {
    asm volatile("ldmatrix.sync.aligned.m8n8.x4.trans.shared.b16 {%0,%1,%2,%3}, [%4];"
                 : "=r"(r[0]), "=r"(r[1]), "=r"(r[2]), "=r"(r[3]) : "r"(addr));
}
__device__ __forceinline__ void mma_f16(float* c, const uint32_t* a, uint32_t b0, uint32_t b1) {
    asm volatile(
        "mma.sync.aligned.m16n8k16.row.col.f32.f16.f16.f32 "
        "{%0,%1,%2,%3}, {%4,%5,%6,%7}, {%8,%9}, {%0,%1,%2,%3};"
        : "+f"(c[0]), "+f"(c[1]), "+f"(c[2]), "+f"(c[3])
        : "r"(a[0]), "r"(a[1]), "r"(a[2]), "r"(a[3]), "r"(b0), "r"(b1));
}
__device__ __forceinline__ uint32_t h2u(float a, float b) {
    __half2 h = __floats2half2_rn(a, b);
    return *reinterpret_cast<uint32_t*>(&h);
}

// ---------------- weights fp32 -> fp16 (all four in one launch) ----------------
__global__ void cvt_all_kernel(
    const float4* __restrict__ i0, __half2* __restrict__ o0, int n0,
    const float4* __restrict__ i1, __half2* __restrict__ o1, int n1,
    const float4* __restrict__ i2, __half2* __restrict__ o2, int n2,
    const float4* __restrict__ i3, __half2* __restrict__ o3, int n3)
{
    int i = blockIdx.x * blockDim.x + threadIdx.x;
    const float4* in; __half2* out; int idx;
    if (i < n0)                { in = i0; out = o0; idx = i; }
    else if (i < n0+n1)        { in = i1; out = o1; idx = i - n0; }
    else if (i < n0+n1+n2)     { in = i2; out = o2; idx = i - n0 - n1; }
    else if (i < n0+n1+n2+n3)  { in = i3; out = o3; idx = i - n0 - n1 - n2; }
    else return;
    float4 v = in[idx];
    out[2*idx]   = __floats2half2_rn(v.x, v.y);
    out[2*idx+1] = __floats2half2_rn(v.z, v.w);
}

// ---------------- LayerNorm (fp16 out) ----------------
__inline__ __device__ float warp_sum(float v) {
    #pragma unroll
    for (int o = 16; o; o >>= 1) v += __shfl_xor_sync(0xffffffffu, v, o);
    return v;
}

__global__ void __launch_bounds__(256) ln_kernel(
    const float* __restrict__ x, const float* __restrict__ w,
    const float* __restrict__ b, __half* __restrict__ y)
{
    __shared__ float rs[8], rq[8];
    __shared__ float s_mean, s_rstd;
    int row = blockIdx.x;
    int tid = threadIdx.x;
    const float* xr = x + (size_t)row * EMB;
    float v0 = xr[tid], v1 = xr[tid + 256], v2 = xr[tid + 512];
    float s = v0 + v1 + v2;
    float q = v0*v0 + v1*v1 + v2*v2;
    s = warp_sum(s); q = warp_sum(q);
    int wid = tid >> 5, lane = tid & 31;
    if (lane == 0) { rs[wid] = s; rq[wid] = q; }
    __syncthreads();
    if (tid == 0) {
        float S = 0.f, Q = 0.f;
        #pragma unroll
        for (int i = 0; i < 8; i++) { S += rs[i]; Q += rq[i]; }
        float mean = S * (1.0f / EMB);
        float var  = Q * (1.0f / EMB) - mean * mean;
        s_mean = mean;
        s_rstd = rsqrtf(var + 1e-5f);
    }
    __syncthreads();
    float mean = s_mean, rstd = s_rstd;
    __half* yr = y + (size_t)row * EMB;
    yr[tid]       = __float2half_rn((v0 - mean) * rstd * w[tid]       + b[tid]);
    yr[tid + 256] = __float2half_rn((v1 - mean) * rstd * w[tid + 256] + b[tid + 256]);
    yr[tid + 512] = __float2half_rn((v2 - mean) * rstd * w[tid + 512] + b[tid + 512]);
}

// ---------------- fp16 mma.sync GEMM, 3-stage pipeline ----------------
// Tile 128x128, BK=64, 8 warps (2M x 4N), warp tile 64x32.
// smem rows: 64 fp16 (128B) in 144B stride. ONE __syncthreads per iteration.
// MODE: 0 = bias, 1 = bias + residual, 2 = bias + QuickGELU
#define SB    144
#define GBUF  (128 * SB)                 // 18432 B
#define TCG_SMEM_BYTES (6 * GBUF)        // 110592

template<int MODE, typename OutT>
__global__ void __launch_bounds__(256, 2) tc_gemm(
    const __half* __restrict__ A, const __half* __restrict__ B,
    const float* __restrict__ bias, const float* __restrict__ res,
    OutT* __restrict__ C, int M, int N, int K)
{
    extern __shared__ char smc[];
    uint32_t sbase = smem_u32(smc);

    int tid = threadIdx.x;
    int wp = tid >> 5, lane = tid & 31;
    int wm = wp & 1, wn = wp >> 1;

    int m0 = blockIdx.y * 128, n0 = blockIdx.x * 128;

    int rS[4], cS[4];
    #pragma unroll
    for (int i = 0; i < 4; i++) { int f = tid + 256 * i; rS[i] = f >> 3; cS[i] = f & 7; }

    const int NSTG = K >> 6;

    #pragma unroll
    for (int st = 0; st < 2; st++) {
        int k0 = st << 6;
        #pragma unroll
        for (int i = 0; i < 4; i++) {
            uint32_t so = (uint32_t)(rS[i] * SB + cS[i] * 16);
            CP_ASYNC16(sbase + (uint32_t)(st * GBUF) + so,       A + (size_t)(m0 + rS[i]) * K + k0 + cS[i] * 8);
            CP_ASYNC16(sbase + (uint32_t)((3 + st) * GBUF) + so, B + (size_t)(n0 + rS[i]) * K + k0 + cS[i] * 8);
        }
        CP_COMMIT();
    }

    float acc[4][4][4];
    #pragma unroll
    for (int mf = 0; mf < 4; mf++)
        #pragma unroll
        for (int nf = 0; nf < 4; nf++)
            #pragma unroll
            for (int r = 0; r < 4; r++) acc[mf][nf][r] = 0.f;

    uint32_t a_base = (uint32_t)((wm * 64 + (lane & 15)) * SB + (lane >> 4) * 16);
    uint32_t b_base = (uint32_t)((wn * 32 + (lane & 15)) * SB + (lane >> 4) * 16);

    for (int it = 0; it < NSTG; it++) {
        CP_WAITG(1);
        __syncthreads();
        if (it + 2 < NSTG) {
            int st = (it + 2) % 3;
            int k0 = (it + 2) << 6;
            #pragma unroll
            for (int i = 0; i < 4; i++) {
                uint32_t so = (uint32_t)(rS[i] * SB + cS[i] * 16);
                CP_ASYNC16(sbase + (uint32_t)(st * GBUF) + so,       A + (size_t)(m0 + rS[i]) * K + k0 + cS[i] * 8);
                CP_ASYNC16(sbase + (uint32_t)((3 + st) * GBUF) + so, B + (size_t)(n0 + rS[i]) * K + k0 + cS[i] * 8);
            }
        }
        CP_COMMIT();

        int cur = it % 3;
        uint32_t ab = sbase + (uint32_t)(cur * GBUF) + a_base;
        uint32_t bb = sbase + (uint32_t)((3 + cur) * GBUF) + b_base;
        #pragma unroll
        for (int ks = 0; ks < 4; ks++) {
            uint32_t afr[4][4];
            #pragma unroll
            for (int mf = 0; mf < 4; mf++)
                ldmx4(afr[mf], ab + (uint32_t)(mf * 16 * SB + ks * 32));
            uint32_t b0f[4], b1f[4];
            ldmx4(b0f, bb + (uint32_t)(ks * 32));
            ldmx4(b1f, bb + (uint32_t)(16 * SB + ks * 32));
            #pragma unroll
            for (int mf = 0; mf < 4; mf++) {
                mma_f16(acc[mf][0], afr[mf], b0f[0], b0f[2]);
                mma_f16(acc[mf][1], afr[mf], b0f[1], b0f[3]);
                mma_f16(acc[mf][2], afr[mf], b1f[0], b1f[2]);
                mma_f16(acc[mf][3], afr[mf], b1f[1], b1f[3]);
            }
        }
    }

    int g = lane >> 2, q = lane & 3;
    #pragma unroll
    for (int mf = 0; mf < 4; mf++) {
        int r0 = m0 + wm * 64 + mf * 16 + g;
        #pragma unroll
        for (int nf = 0; nf < 4; nf++) {
            int col = n0 + wn * 32 + nf * 8 + 2 * q;
            float b0 = bias[col], b1 = bias[col + 1];
            float v0 = acc[mf][nf][0] + b0;
            float v1 = acc[mf][nf][1] + b1;
            float v2 = acc[mf][nf][2] + b0;
            float v3 = acc[mf][nf][3] + b1;
            if (MODE == 1) {
                const float* rp0 = res + (size_t)r0 * N + col;
                const float* rp1 = res + (size_t)(r0 + 8) * N + col;
                v0 += rp0[0]; v1 += rp0[1];
                v2 += rp1[0]; v3 += rp1[1];
            }
            if (MODE == 2) {
                v0 = v0 / (1.0f + __expf(-1.702f * v0));
                v1 = v1 / (1.0f + __expf(-1.702f * v1));
                v2 = v2 / (1.0f + __expf(-1.702f * v2));
                v3 = v3 / (1.0f + __expf(-1.702f * v3));
            }
            if (sizeof(OutT) == 2) {
                *(__half2*)((__half*)C + (size_t)r0 * N + col)       = __floats2half2_rn(v0, v1);
                *(__half2*)((__half*)C + (size_t)(r0 + 8) * N + col) = __floats2half2_rn(v2, v3);
            } else {
                *(float2*)((float*)C + (size_t)r0 * N + col)       = make_float2(v0, v1);
                *(float2*)((float*)C + (size_t)(r0 + 8) * N + col) = make_float2(v2, v3);
            }
        }
    }
}

// ---------------- fp16 mma.sync flash attention, 128q tile ----------------
// grid (SEQ/128, BATCH*NHEAD), 256 threads (8 warps); warp w owns q-rows w*16..+16.
// K/V loaded once per 128 queries (halved traffic vs 64q tile).
// smem fp16, 144B stride: Q[128] | K0 K1 K2 | V0 V1 V2  (64-row stages)
#define QTILE 18432                      // 128 * 144
#define ATILE 9216                       // 64 * 144
#define ATTN_SMEM_BYTES (QTILE + 6 * ATILE)   // 73728

__global__ void __launch_bounds__(256) attn_kernel(
    const __half* __restrict__ qkv, __half* __restrict__ out)
{
    extern __shared__ char sma[];
    uint32_t sb = smem_u32(sma);

    int tid = threadIdx.x;
    int w = tid >> 5, lane = tid & 31;
    int g = lane >> 2, qd = lane & 3;
    int nh = blockIdx.y;
    int n = nh / NHEAD, h = nh % NHEAD;
    int q0 = blockIdx.x * 128;

    const size_t GROW = (size_t)BATCH * 3 * EMB;   // halves per seq step

    // Q staging: 128 rows x 8 chunks = 1024 chunks, 4 per thread
    int rQ[4], cQ[4];
    #pragma unroll
    for (int i = 0; i < 4; i++) { int f = tid + 256 * i; rQ[i] = f >> 3; cQ[i] = f & 7; }
    // K/V staging: 64 rows x 8 chunks = 512 chunks, 2 per thread each
    int rT[2], cT[2];
    #pragma unroll
    for (int i = 0; i < 2; i++) { int f = tid + 256 * i; rT[i] = f >> 3; cT[i] = f & 7; }

    const __half* qbase = qkv + ((size_t)q0 * BATCH + n) * (3 * EMB) + h * DH;
    const __half* kroot = qkv + (size_t)n * (3 * EMB) + EMB + h * DH;

    // commit0 = {Q, K0, V0}; commit1 = {K1, V1}
    #pragma unroll
    for (int i = 0; i < 4; i++) {
        uint32_t so = (uint32_t)(rQ[i] * SB + cQ[i] * 16);
        CP_ASYNC16(sb + so, qbase + (size_t)rQ[i] * GROW + cQ[i] * 8);
    }
    #pragma unroll
    for (int i = 0; i < 2; i++) {
        uint32_t so = (uint32_t)(rT[i] * SB + cT[i] * 16);
        const __half* src = kroot + (size_t)rT[i] * GROW + cT[i] * 8;
        CP_ASYNC16(sb + (uint32_t)QTILE + so, src);
        CP_ASYNC16(sb + (uint32_t)(QTILE + 3 * ATILE) + so, src + EMB);
    }
    CP_COMMIT();
    #pragma unroll
    for (int i = 0; i < 2; i++) {
        uint32_t so = (uint32_t)(rT[i] * SB + cT[i] * 16);
        const __half* src = kroot + (size_t)(64 + rT[i]) * GROW + cT[i] * 8;
        CP_ASYNC16(sb + (uint32_t)(QTILE + ATILE) + so, src);
        CP_ASYNC16(sb + (uint32_t)(QTILE + 4 * ATILE) + so, src + EMB);
    }
    CP_COMMIT();

    float m0r = -1e30f, m1r = -1e30f, l0r = 0.f, l1r = 0.f;
    float o[8][4];
    #pragma unroll
    for (int i = 0; i < 8; i++)
        #pragma unroll
        for (int j = 0; j < 4; j++) o[i][j] = 0.f;

    const uint32_t frag = (uint32_t)((lane & 15) * SB + (lane >> 4) * 16);
    const uint32_t a_q = sb + (uint32_t)(w * 16 * SB) + frag;

    const int NT = SEQ / 64;
    for (int t = 0; t < NT; t++) {
        CP_WAITG(1);
        __syncthreads();
        if (t + 2 < NT) {
            int st = (t + 2) % 3;
            const __half* kb = kroot + (size_t)((t + 2) * 64) * GROW;
            #pragma unroll
            for (int i = 0; i < 2; i++) {
                uint32_t so = (uint32_t)(rT[i] * SB + cT[i] * 16);
                const __half* src = kb + (size_t)rT[i] * GROW + cT[i] * 8;
                CP_ASYNC16(sb + (uint32_t)(QTILE + st * ATILE) + so, src);
                CP_ASYNC16(sb + (uint32_t)(QTILE + (3 + st) * ATILE) + so, src + EMB);
            }
        }
        CP_COMMIT();

        int cur = t % 3;
        uint32_t kbuf = sb + (uint32_t)(QTILE + cur * ATILE);
        uint32_t vbuf = sb + (uint32_t)(QTILE + (3 + cur) * ATILE);

        // S = Q @ K^T  (16q x 64k per warp)
        float s4[8][4];
        #pragma unroll
        for (int i = 0; i < 8; i++)
            #pragma unroll
            for (int j = 0; j < 4; j++) s4[i][j] = 0.f;
        #pragma unroll
        for (int kd = 0; kd < 4; kd++) {
            uint32_t aq[4];
            ldmx4(aq, a_q + (uint32_t)(kd * 32));
            #pragma unroll
            for (int j = 0; j < 4; j++) {
                uint32_t bk[4];
                ldmx4(bk, kbuf + (uint32_t)(j * 16 * SB + kd * 32) + frag);
                mma_f16(s4[2*j+0], aq, bk[0], bk[2]);
                mma_f16(s4[2*j+1], aq, bk[1], bk[3]);
            }
        }
        #pragma unroll
        for (int i = 0; i < 8; i++)
            #pragma unroll
            for (int j = 0; j < 4; j++) s4[i][j] *= 0.125f;

        // online softmax
        float rm0 = -1e30f, rm1 = -1e30f;
        #pragma unroll
        for (int i = 0; i < 8; i++) {
            rm0 = fmaxf(rm0, fmaxf(s4[i][0], s4[i][1]));
            rm1 = fmaxf(rm1, fmaxf(s4[i][2], s4[i][3]));
        }
        rm0 = fmaxf(rm0, __shfl_xor_sync(0xffffffffu, rm0, 1));
        rm0 = fmaxf(rm0, __shfl_xor_sync(0xffffffffu, rm0, 2));
        rm1 = fmaxf(rm1, __shfl_xor_sync(0xffffffffu, rm1, 1));
        rm1 = fmaxf(rm1, __shfl_xor_sync(0xffffffffu, rm1, 2));
        float mn0 = fmaxf(m0r, rm0), mn1 = fmaxf(m1r, rm1);
        float f0 = __expf(m0r - mn0), f1 = __expf(m1r - mn1);
        m0r = mn0; m1r = mn1;

        uint32_t pa[4][4];
        float rs0 = 0.f, rs1 = 0.f;
        #pragma unroll
        for (int j = 0; j < 4; j++) {
            float pa0 = __expf(s4[2*j+0][0] - mn0), pa1 = __expf(s4[2*j+0][1] - mn0);
            float pa2 = __expf(s4[2*j+0][2] - mn1), pa3 = __expf(s4[2*j+0][3] - mn1);
            float pb0 = __expf(s4[2*j+1][0] - mn0), pb1 = __expf(s4[2*j+1][1] - mn0);
            float pb2 = __expf(s4[2*j+1][2] - mn1), pb3 = __expf(s4[2*j+1][3] - mn1);
            rs0 += pa0 + pa1 + pb0 + pb1;
            rs1 += pa2 + pa3 + pb2 + pb3;
            pa[j][0] = h2u(pa0, pa1);
            pa[j][1] = h2u(pa2, pa3);
            pa[j][2] = h2u(pb0, pb1);
            pa[j][3] = h2u(pb2, pb3);
        }
        rs0 += __shfl_xor_sync(0xffffffffu, rs0, 1);
        rs0 += __shfl_xor_sync(0xffffffffu, rs0, 2);
        rs1 += __shfl_xor_sync(0xffffffffu, rs1, 1);
        rs1 += __shfl_xor_sync(0xffffffffu, rs1, 2);
        l0r = l0r * f0 + rs0;
        l1r = l1r * f1 + rs1;

        #pragma unroll
        for (int i = 0; i < 8; i++) {
            o[i][0] *= f0; o[i][1] *= f0; o[i][2] *= f1; o[i][3] *= f1;
        }

        // O += P @ V
        #pragma unroll
        for (int ks = 0; ks < 4; ks++) {
            #pragma unroll
            for (int t4 = 0; t4 < 4; t4++) {
                uint32_t bv[4];
                ldmx4t(bv, vbuf + (uint32_t)(ks * 16 * SB + t4 * 32) + frag);
                mma_f16(o[2*t4+0], pa[ks], bv[0], bv[1]);
                mma_f16(o[2*t4+1], pa[ks], bv[2], bv[3]);
            }
        }
    }

    // epilogue (fp16 out)
    float inv0 = 1.0f / l0r, inv1 = 1.0f / l1r;
    int row0 = q0 + w * 16 + g;
    #pragma unroll
    for (int jj = 0; jj < 8; jj++) {
        int col = jj * 8 + 2 * qd;
        __half* op0 = out + ((size_t)row0 * BATCH + n) * EMB + h * DH + col;
        __half* op1 = out + ((size_t)(row0 + 8) * BATCH + n) * EMB + h * DH + col;
        *(__half2*)op0 = __floats2half2_rn(o[jj][0] * inv0, o[jj][1] * inv0);
        *(__half2*)op1 = __floats2half2_rn(o[jj][2] * inv1, o[jj][3] * inv1);
    }
}

// ---------------- launch ----------------
extern "C" void kernel_launch(void* const* d_in, const int* in_sizes, int n_in,
                              void* d_out, int out_size)
{
    const float* x      = (const float*)d_in[0];
    const float* ln1_w  = (const float*)d_in[1];
    const float* ln1_b  = (const float*)d_in[2];
    const float* w_qkv  = (const float*)d_in[3];
    const float* b_qkv  = (const float*)d_in[4];
    const float* w_out  = (const float*)d_in[5];
    const float* b_out  = (const float*)d_in[6];
    const float* ln2_w  = (const float*)d_in[7];
    const float* ln2_b  = (const float*)d_in[8];
    const float* w_fc   = (const float*)d_in[9];
    const float* b_fc   = (const float*)d_in[10];
    const float* w_proj = (const float*)d_in[11];
    const float* b_proj = (const float*)d_in[12];
    float* out = (float*)d_out;

    void *p_hb, *p_qkvh, *p_attnb, *p_x1, *p_fb, *p_wq, *p_wo, *p_wf, *p_wp;
    cudaGetSymbolAddress(&p_hb, g_hb);
    cudaGetSymbolAddress(&p_qkvh, g_qkvh);
    cudaGetSymbolAddress(&p_attnb, g_attnb);
    cudaGetSymbolAddress(&p_x1, g_x1);
    cudaGetSymbolAddress(&p_fb, g_fb);
    cudaGetSymbolAddress(&p_wq, g_wq);
    cudaGetSymbolAddress(&p_wo, g_wo);
    cudaGetSymbolAddress(&p_wf, g_wf);
    cudaGetSymbolAddress(&p_wp, g_wp);
    __half* hb    = (__half*)p_hb;
    __half* qkvh  = (__half*)p_qkvh;
    __half* attnb = (__half*)p_attnb;
    float*  x1b   = (float*)p_x1;
    __half* fb    = (__half*)p_fb;
    __half* wq  = (__half*)p_wq;
    __half* wo  = (__half*)p_wo;
    __half* wf  = (__half*)p_wf;
    __half* wpj = (__half*)p_wp;

    cudaFuncSetAttribute(attn_kernel, cudaFuncAttributeMaxDynamicSharedMemorySize,
                         ATTN_SMEM_BYTES);
    cudaFuncSetAttribute(tc_gemm<0, __half>, cudaFuncAttributeMaxDynamicSharedMemorySize, TCG_SMEM_BYTES);
    cudaFuncSetAttribute(tc_gemm<1, float>, cudaFuncAttributeMaxDynamicSharedMemorySize, TCG_SMEM_BYTES);
    cudaFuncSetAttribute(tc_gemm<2, __half>, cudaFuncAttributeMaxDynamicSharedMemorySize, TCG_SMEM_BYTES);

    // 0) weights -> fp16 (single launch)
    {
        int n0 = 3*EMB*EMB/4, n1 = EMB*EMB/4, n2 = 4*EMB*EMB/4, n3 = 4*EMB*EMB/4;
        int total = n0 + n1 + n2 + n3;
        cvt_all_kernel<<<(total + 255) / 256, 256>>>(
            (const float4*)w_qkv,  (__half2*)wq,  n0,
            (const float4*)w_out,  (__half2*)wo,  n1,
            (const float4*)w_fc,   (__half2*)wf,  n2,
            (const float4*)w_proj, (__half2*)wpj, n3);
    }

    // 1) h = LN1(x)  (fp16)
    ln_kernel<<<ROWS, 256>>>(x, ln1_w, ln1_b, hb);
    // 2) qkv = h @ w_qkv^T + b_qkv  (fp16 out)
    tc_gemm<0, __half><<<dim3(3*EMB/128, ROWS/128), 256, TCG_SMEM_BYTES>>>(
        hb, wq, b_qkv, nullptr, qkvh, ROWS, 3*EMB, EMB);
    // 3) attention (fp16 flash, 128q tile; fp16 out)
    attn_kernel<<<dim3(SEQ/128, BATCH*NHEAD), 256, ATTN_SMEM_BYTES>>>(qkvh, attnb);
    // 4) x1 = x + attn @ w_out^T + b_out  (fp32 out)
    tc_gemm<1, float><<<dim3(EMB/128, ROWS/128), 256, TCG_SMEM_BYTES>>>(
        attnb, wo, b_out, x, x1b, ROWS, EMB, EMB);
    // 5) h = LN2(x1)  (fp16)
    ln_kernel<<<ROWS, 256>>>(x1b, ln2_w, ln2_b, hb);
    // 6) f = QuickGELU(h @ w_fc^T + b_fc)  (fp16 out)
    tc_gemm<2, __half><<<dim3(4*EMB/128, ROWS/128), 256, TCG_SMEM_BYTES>>>(
        hb, wf, b_fc, nullptr, fb, ROWS, 4*EMB, EMB);
    // 7) out = x1 + f @ w_proj^T + b_proj  (fp32 out)
    tc_gemm<1, float><<<dim3(EMB/128, ROWS/128), 256, TCG_SMEM_BYTES>>>(
        fb, wpj, b_proj, x1b, out, ROWS, EMB, 4*EMB);
}

// round 12
// speedup vs baseline: 6.9228x; 1.0301x over previous
#include <cuda_runtime.h>
#include <cuda_fp16.h>
#include <math.h>
#include <cstdint>

#define SEQ   2048
#define BATCH 4
#define EMB   768
#define NHEAD 12
#define DH    64
#define ROWS  (SEQ*BATCH)   // 8192

// ---------------- scratch (device globals; allocation-free) ----------------
__device__ __align__(16) __half g_hb[ROWS * EMB];        // LN out (fp16)
__device__ __align__(16) __half g_qkvh[ROWS * 3 * EMB];  // qkv (fp16)
__device__ __align__(16) __half g_attnb[ROWS * EMB];     // attn out (fp16)
__device__ float g_x1[ROWS * EMB];                       // x + attn_out (fp32)
__device__ __align__(16) __half g_fb[ROWS * 4 * EMB];    // MLP hidden (fp16)
// fp16 weight copies
__device__ __align__(16) __half g_wq[3 * EMB * EMB];
__device__ __align__(16) __half g_wo[EMB * EMB];
__device__ __align__(16) __half g_wf[4 * EMB * EMB];
__device__ __align__(16) __half g_wp[4 * EMB * EMB];

// ================= helpers =================
__device__ __forceinline__ uint32_t smem_u32(const void* p) {
    uint32_t a;
    asm("{ .reg .u64 t; cvta.to.shared.u64 t, %1; cvt.u32.u64 %0, t; }" : "=r"(a) : "l"(p));
    return a;
}
__device__ __forceinline__ float ex2f(float x) {
    float y;
    asm("ex2.approx.ftz.f32 %0, %1;" : "=f"(y) : "f"(x));
    return y;
}
#define CP_ASYNC16(dst, src) \
    asm volatile("cp.async.cg.shared.global [%0], [%1], 16;" :: "r"(dst), "l"(src) : "memory")
#define CP_COMMIT() asm volatile("cp.async.commit_group;" ::: "memory")
#define CP_WAITG(n) asm volatile("cp.async.wait_group %0;" :: "n"(n) : "memory")

__device__ __forceinline__ void ldmx4(uint32_t* r, uint32_t addr) {
    asm volatile("ldmatrix.sync.aligned.m8n8.x4.shared.b16 {%0,%1,%2,%3}, [%4];"
                 : "=r"(r[0]), "=r"(r[1]), "=r"(r[2]), "=r"(r[3]) : "r"(addr));
}
__device__ __forceinline__ void ldmx4t(uint32_t* r, uint32_t addr) {
    asm volatile("ldmatrix.sync.aligned.m8n8.x4.trans.shared.b16 {%0,%1,%2,%3}, [%4];"
                 : "=r"(r[0]), "=r"(r[1]), "=r"(r[2]), "=r"(r[3]) : "r"(addr));
}
__device__ __forceinline__ void mma_f16(float* c, const uint32_t* a, uint32_t b0, uint32_t b1) {
    asm volatile(
        "mma.sync.aligned.m16n8k16.row.col.f32.f16.f16.f32 "
        "{%0,%1,%2,%3}, {%4,%5,%6,%7}, {%8,%9}, {%0,%1,%2,%3};"
        : "+f"(c[0]), "+f"(c[1]), "+f"(c[2]), "+f"(c[3])
        : "r"(a[0]), "r"(a[1]), "r"(a[2]), "r"(a[3]), "r"(b0), "r"(b1));
}
__device__ __forceinline__ uint32_t h2u(float a, float b) {
    __half2 h = __floats2half2_rn(a, b);
    return *reinterpret_cast<uint32_t*>(&h);
}

// ---------------- weights fp32 -> fp16 (all four in one launch) ----------------
__global__ void cvt_all_kernel(
    const float4* __restrict__ i0, __half2* __restrict__ o0, int n0,
    const float4* __restrict__ i1, __half2* __restrict__ o1, int n1,
    const float4* __restrict__ i2, __half2* __restrict__ o2, int n2,
    const float4* __restrict__ i3, __half2* __restrict__ o3, int n3)
{
    int i = blockIdx.x * blockDim.x + threadIdx.x;
    const float4* in; __half2* out; int idx;
    if (i < n0)                { in = i0; out = o0; idx = i; }
    else if (i < n0+n1)        { in = i1; out = o1; idx = i - n0; }
    else if (i < n0+n1+n2)     { in = i2; out = o2; idx = i - n0 - n1; }
    else if (i < n0+n1+n2+n3)  { in = i3; out = o3; idx = i - n0 - n1 - n2; }
    else return;
    float4 v = in[idx];
    out[2*idx]   = __floats2half2_rn(v.x, v.y);
    out[2*idx+1] = __floats2half2_rn(v.z, v.w);
}

// ---------------- LayerNorm (fp16 out) ----------------
__inline__ __device__ float warp_sum(float v) {
    #pragma unroll
    for (int o = 16; o; o >>= 1) v += __shfl_xor_sync(0xffffffffu, v, o);
    return v;
}

__global__ void __launch_bounds__(256) ln_kernel(
    const float* __restrict__ x, const float* __restrict__ w,
    const float* __restrict__ b, __half* __restrict__ y)
{
    __shared__ float rs[8], rq[8];
    __shared__ float s_mean, s_rstd;
    int row = blockIdx.x;
    int tid = threadIdx.x;
    const float* xr = x + (size_t)row * EMB;
    float v0 = xr[tid], v1 = xr[tid + 256], v2 = xr[tid + 512];
    float s = v0 + v1 + v2;
    float q = v0*v0 + v1*v1 + v2*v2;
    s = warp_sum(s); q = warp_sum(q);
    int wid = tid >> 5, lane = tid & 31;
    if (lane == 0) { rs[wid] = s; rq[wid] = q; }
    __syncthreads();
    if (tid == 0) {
        float S = 0.f, Q = 0.f;
        #pragma unroll
        for (int i = 0; i < 8; i++) { S += rs[i]; Q += rq[i]; }
        float mean = S * (1.0f / EMB);
        float var  = Q * (1.0f / EMB) - mean * mean;
        s_mean = mean;
        s_rstd = rsqrtf(var + 1e-5f);
    }
    __syncthreads();
    float mean = s_mean, rstd = s_rstd;
    __half* yr = y + (size_t)row * EMB;
    yr[tid]       = __float2half_rn((v0 - mean) * rstd * w[tid]       + b[tid]);
    yr[tid + 256] = __float2half_rn((v1 - mean) * rstd * w[tid + 256] + b[tid + 256]);
    yr[tid + 512] = __float2half_rn((v2 - mean) * rstd * w[tid + 512] + b[tid + 512]);
}

// ---------------- fp16 mma.sync GEMM, 3-stage pipeline (unchanged) ----------------
#define SB    144
#define GBUF  (128 * SB)                 // 18432 B
#define TCG_SMEM_BYTES (6 * GBUF)        // 110592

template<int MODE, typename OutT>
__global__ void __launch_bounds__(256, 2) tc_gemm(
    const __half* __restrict__ A, const __half* __restrict__ B,
    const float* __restrict__ bias, const float* __restrict__ res,
    OutT* __restrict__ C, int M, int N, int K)
{
    extern __shared__ char smc[];
    uint32_t sbase = smem_u32(smc);

    int tid = threadIdx.x;
    int wp = tid >> 5, lane = tid & 31;
    int wm = wp & 1, wn = wp >> 1;

    int m0 = blockIdx.y * 128, n0 = blockIdx.x * 128;

    int rS[4], cS[4];
    #pragma unroll
    for (int i = 0; i < 4; i++) { int f = tid + 256 * i; rS[i] = f >> 3; cS[i] = f & 7; }

    const int NSTG = K >> 6;

    #pragma unroll
    for (int st = 0; st < 2; st++) {
        int k0 = st << 6;
        #pragma unroll
        for (int i = 0; i < 4; i++) {
            uint32_t so = (uint32_t)(rS[i] * SB + cS[i] * 16);
            CP_ASYNC16(sbase + (uint32_t)(st * GBUF) + so,       A + (size_t)(m0 + rS[i]) * K + k0 + cS[i] * 8);
            CP_ASYNC16(sbase + (uint32_t)((3 + st) * GBUF) + so, B + (size_t)(n0 + rS[i]) * K + k0 + cS[i] * 8);
        }
        CP_COMMIT();
    }

    float acc[4][4][4];
    #pragma unroll
    for (int mf = 0; mf < 4; mf++)
        #pragma unroll
        for (int nf = 0; nf < 4; nf++)
            #pragma unroll
            for (int r = 0; r < 4; r++) acc[mf][nf][r] = 0.f;

    uint32_t a_base = (uint32_t)((wm * 64 + (lane & 15)) * SB + (lane >> 4) * 16);
    uint32_t b_base = (uint32_t)((wn * 32 + (lane & 15)) * SB + (lane >> 4) * 16);

    for (int it = 0; it < NSTG; it++) {
        CP_WAITG(1);
        __syncthreads();
        if (it + 2 < NSTG) {
            int st = (it + 2) % 3;
            int k0 = (it + 2) << 6;
            #pragma unroll
            for (int i = 0; i < 4; i++) {
                uint32_t so = (uint32_t)(rS[i] * SB + cS[i] * 16);
                CP_ASYNC16(sbase + (uint32_t)(st * GBUF) + so,       A + (size_t)(m0 + rS[i]) * K + k0 + cS[i] * 8);
                CP_ASYNC16(sbase + (uint32_t)((3 + st) * GBUF) + so, B + (size_t)(n0 + rS[i]) * K + k0 + cS[i] * 8);
            }
        }
        CP_COMMIT();

        int cur = it % 3;
        uint32_t ab = sbase + (uint32_t)(cur * GBUF) + a_base;
        uint32_t bb = sbase + (uint32_t)((3 + cur) * GBUF) + b_base;
        #pragma unroll
        for (int ks = 0; ks < 4; ks++) {
            uint32_t afr[4][4];
            #pragma unroll
            for (int mf = 0; mf < 4; mf++)
                ldmx4(afr[mf], ab + (uint32_t)(mf * 16 * SB + ks * 32));
            uint32_t b0f[4], b1f[4];
            ldmx4(b0f, bb + (uint32_t)(ks * 32));
            ldmx4(b1f, bb + (uint32_t)(16 * SB + ks * 32));
            #pragma unroll
            for (int mf = 0; mf < 4; mf++) {
                mma_f16(acc[mf][0], afr[mf], b0f[0], b0f[2]);
                mma_f16(acc[mf][1], afr[mf], b0f[1], b0f[3]);
                mma_f16(acc[mf][2], afr[mf], b1f[0], b1f[2]);
                mma_f16(acc[mf][3], afr[mf], b1f[1], b1f[3]);
            }
        }
    }

    int g = lane >> 2, q = lane & 3;
    #pragma unroll
    for (int mf = 0; mf < 4; mf++) {
        int r0 = m0 + wm * 64 + mf * 16 + g;
        #pragma unroll
        for (int nf = 0; nf < 4; nf++) {
            int col = n0 + wn * 32 + nf * 8 + 2 * q;
            float b0 = bias[col], b1 = bias[col + 1];
            float v0 = acc[mf][nf][0] + b0;
            float v1 = acc[mf][nf][1] + b1;
            float v2 = acc[mf][nf][2] + b0;
            float v3 = acc[mf][nf][3] + b1;
            if (MODE == 1) {
                const float* rp0 = res + (size_t)r0 * N + col;
                const float* rp1 = res + (size_t)(r0 + 8) * N + col;
                v0 += rp0[0]; v1 += rp0[1];
                v2 += rp1[0]; v3 += rp1[1];
            }
            if (MODE == 2) {
                v0 = v0 / (1.0f + __expf(-1.702f * v0));
                v1 = v1 / (1.0f + __expf(-1.702f * v1));
                v2 = v2 / (1.0f + __expf(-1.702f * v2));
                v3 = v3 / (1.0f + __expf(-1.702f * v3));
            }
            if (sizeof(OutT) == 2) {
                *(__half2*)((__half*)C + (size_t)r0 * N + col)       = __floats2half2_rn(v0, v1);
                *(__half2*)((__half*)C + (size_t)(r0 + 8) * N + col) = __floats2half2_rn(v2, v3);
            } else {
                *(float2*)((float*)C + (size_t)r0 * N + col)       = make_float2(v0, v1);
                *(float2*)((float*)C + (size_t)(r0 + 8) * N + col) = make_float2(v2, v3);
            }
        }
    }
}

// ---------------- fp16 mma.sync flash attention, 128q tile ----------------
// grid (SEQ/128, BATCH*NHEAD), 256 threads (8 warps); warp w owns q-rows w*16..+16.
// Q fragments hoisted to registers (loop-invariant). Softmax via raw ex2 with
// folded 1/sqrt(d)*log2(e) scale; row max over UNSCALED S (shift-invariant).
// smem fp16, 144B stride: Q[128] | K0 K1 K2 | V0 V1 V2  (64-row stages)
#define QTILE 18432                      // 128 * 144
#define ATILE 9216                       // 64 * 144
#define ATTN_SMEM_BYTES (QTILE + 6 * ATILE)   // 73728
#define SM_SCALE_LOG2E 0.1803368801111204f    // 0.125 * log2(e)

__global__ void __launch_bounds__(256) attn_kernel(
    const __half* __restrict__ qkv, __half* __restrict__ out)
{
    extern __shared__ char sma[];
    uint32_t sb = smem_u32(sma);

    int tid = threadIdx.x;
    int w = tid >> 5, lane = tid & 31;
    int g = lane >> 2, qd = lane & 3;
    int nh = blockIdx.y;
    int n = nh / NHEAD, h = nh % NHEAD;
    int q0 = blockIdx.x * 128;

    const size_t GROW = (size_t)BATCH * 3 * EMB;

    int rQ[4], cQ[4];
    #pragma unroll
    for (int i = 0; i < 4; i++) { int f = tid + 256 * i; rQ[i] = f >> 3; cQ[i] = f & 7; }
    int rT[2], cT[2];
    #pragma unroll
    for (int i = 0; i < 2; i++) { int f = tid + 256 * i; rT[i] = f >> 3; cT[i] = f & 7; }

    const __half* qbase = qkv + ((size_t)q0 * BATCH + n) * (3 * EMB) + h * DH;
    const __half* kroot = qkv + (size_t)n * (3 * EMB) + EMB + h * DH;

    // commit0 = {Q, K0, V0}; commit1 = {K1, V1}
    #pragma unroll
    for (int i = 0; i < 4; i++) {
        uint32_t so = (uint32_t)(rQ[i] * SB + cQ[i] * 16);
        CP_ASYNC16(sb + so, qbase + (size_t)rQ[i] * GROW + cQ[i] * 8);
    }
    #pragma unroll
    for (int i = 0; i < 2; i++) {
        uint32_t so = (uint32_t)(rT[i] * SB + cT[i] * 16);
        const __half* src = kroot + (size_t)rT[i] * GROW + cT[i] * 8;
        CP_ASYNC16(sb + (uint32_t)QTILE + so, src);
        CP_ASYNC16(sb + (uint32_t)(QTILE + 3 * ATILE) + so, src + EMB);
    }
    CP_COMMIT();
    #pragma unroll
    for (int i = 0; i < 2; i++) {
        uint32_t so = (uint32_t)(rT[i] * SB + cT[i] * 16);
        const __half* src = kroot + (size_t)(64 + rT[i]) * GROW + cT[i] * 8;
        CP_ASYNC16(sb + (uint32_t)(QTILE + ATILE) + so, src);
        CP_ASYNC16(sb + (uint32_t)(QTILE + 4 * ATILE) + so, src + EMB);
    }
    CP_COMMIT();

    const uint32_t frag = (uint32_t)((lane & 15) * SB + (lane >> 4) * 16);
    const uint32_t a_q = sb + (uint32_t)(w * 16 * SB) + frag;

    // wait for commit group 0 (Q, K0, V0), hoist Q fragments into registers
    CP_WAITG(1);
    __syncthreads();
    uint32_t qf[4][4];
    #pragma unroll
    for (int kd = 0; kd < 4; kd++)
        ldmx4(qf[kd], a_q + (uint32_t)(kd * 32));

    float m0r = -1e30f, m1r = -1e30f, l0r = 0.f, l1r = 0.f;
    float o[8][4];
    #pragma unroll
    for (int i = 0; i < 8; i++)
        #pragma unroll
        for (int j = 0; j < 4; j++) o[i][j] = 0.f;

    const int NT = SEQ / 64;
    for (int t = 0; t < NT; t++) {
        CP_WAITG(1);
        __syncthreads();
        if (t + 2 < NT) {
            int st = (t + 2) % 3;
            const __half* kb = kroot + (size_t)((t + 2) * 64) * GROW;
            #pragma unroll
            for (int i = 0; i < 2; i++) {
                uint32_t so = (uint32_t)(rT[i] * SB + cT[i] * 16);
                const __half* src = kb + (size_t)rT[i] * GROW + cT[i] * 8;
                CP_ASYNC16(sb + (uint32_t)(QTILE + st * ATILE) + so, src);
                CP_ASYNC16(sb + (uint32_t)(QTILE + (3 + st) * ATILE) + so, src + EMB);
            }
        }
        CP_COMMIT();

        int cur = t % 3;
        uint32_t kbuf = sb + (uint32_t)(QTILE + cur * ATILE);
        uint32_t vbuf = sb + (uint32_t)(QTILE + (3 + cur) * ATILE);

        // S = Q @ K^T  (16q x 64k per warp), raw (unscaled)
        float s4[8][4];
        #pragma unroll
        for (int i = 0; i < 8; i++)
            #pragma unroll
            for (int j = 0; j < 4; j++) s4[i][j] = 0.f;
        #pragma unroll
        for (int kd = 0; kd < 4; kd++) {
            #pragma unroll
            for (int j = 0; j < 4; j++) {
                uint32_t bk[4];
                ldmx4(bk, kbuf + (uint32_t)(j * 16 * SB + kd * 32) + frag);
                mma_f16(s4[2*j+0], qf[kd], bk[0], bk[2]);
                mma_f16(s4[2*j+1], qf[kd], bk[1], bk[3]);
            }
        }

        // online softmax over raw S with folded scale
        float rm0 = -1e30f, rm1 = -1e30f;
        #pragma unroll
        for (int i = 0; i < 8; i++) {
            rm0 = fmaxf(rm0, fmaxf(s4[i][0], s4[i][1]));
            rm1 = fmaxf(rm1, fmaxf(s4[i][2], s4[i][3]));
        }
        rm0 = fmaxf(rm0, __shfl_xor_sync(0xffffffffu, rm0, 1));
        rm0 = fmaxf(rm0, __shfl_xor_sync(0xffffffffu, rm0, 2));
        rm1 = fmaxf(rm1, __shfl_xor_sync(0xffffffffu, rm1, 1));
        rm1 = fmaxf(rm1, __shfl_xor_sync(0xffffffffu, rm1, 2));
        float mn0 = fmaxf(m0r, rm0), mn1 = fmaxf(m1r, rm1);
        float f0 = ex2f((m0r - mn0) * SM_SCALE_LOG2E);
        float f1 = ex2f((m1r - mn1) * SM_SCALE_LOG2E);
        m0r = mn0; m1r = mn1;
        float nm0 = -mn0 * SM_SCALE_LOG2E, nm1 = -mn1 * SM_SCALE_LOG2E;

        uint32_t pa[4][4];
        float rs0 = 0.f, rs1 = 0.f;
        #pragma unroll
        for (int j = 0; j < 4; j++) {
            float pa0 = ex2f(fmaf(s4[2*j+0][0], SM_SCALE_LOG2E, nm0));
            float pa1 = ex2f(fmaf(s4[2*j+0][1], SM_SCALE_LOG2E, nm0));
            float pa2 = ex2f(fmaf(s4[2*j+0][2], SM_SCALE_LOG2E, nm1));
            float pa3 = ex2f(fmaf(s4[2*j+0][3], SM_SCALE_LOG2E, nm1));
            float pb0 = ex2f(fmaf(s4[2*j+1][0], SM_SCALE_LOG2E, nm0));
            float pb1 = ex2f(fmaf(s4[2*j+1][1], SM_SCALE_LOG2E, nm0));
            float pb2 = ex2f(fmaf(s4[2*j+1][2], SM_SCALE_LOG2E, nm1));
            float pb3 = ex2f(fmaf(s4[2*j+1][3], SM_SCALE_LOG2E, nm1));
            rs0 += pa0 + pa1 + pb0 + pb1;
            rs1 += pa2 + pa3 + pb2 + pb3;
            pa[j][0] = h2u(pa0, pa1);
            pa[j][1] = h2u(pa2, pa3);
            pa[j][2] = h2u(pb0, pb1);
            pa[j][3] = h2u(pb2, pb3);
        }
        rs0 += __shfl_xor_sync(0xffffffffu, rs0, 1);
        rs0 += __shfl_xor_sync(0xffffffffu, rs0, 2);
        rs1 += __shfl_xor_sync(0xffffffffu, rs1, 1);
        rs1 += __shfl_xor_sync(0xffffffffu, rs1, 2);
        l0r = l0r * f0 + rs0;
        l1r = l1r * f1 + rs1;

        #pragma unroll
        for (int i = 0; i < 8; i++) {
            o[i][0] *= f0; o[i][1] *= f0; o[i][2] *= f1; o[i][3] *= f1;
        }

        // O += P @ V
        #pragma unroll
        for (int ks = 0; ks < 4; ks++) {
            #pragma unroll
            for (int t4 = 0; t4 < 4; t4++) {
                uint32_t bv[4];
                ldmx4t(bv, vbuf + (uint32_t)(ks * 16 * SB + t4 * 32) + frag);
                mma_f16(o[2*t4+0], pa[ks], bv[0], bv[1]);
                mma_f16(o[2*t4+1], pa[ks], bv[2], bv[3]);
            }
        }
    }

    // epilogue (fp16 out)
    float inv0 = 1.0f / l0r, inv1 = 1.0f / l1r;
    int row0 = q0 + w * 16 + g;
    #pragma unroll
    for (int jj = 0; jj < 8; jj++) {
        int col = jj * 8 + 2 * qd;
        __half* op0 = out + ((size_t)row0 * BATCH + n) * EMB + h * DH + col;
        __half* op1 = out + ((size_t)(row0 + 8) * BATCH + n) * EMB + h * DH + col;
        *(__half2*)op0 = __floats2half2_rn(o[jj][0] * inv0, o[jj][1] * inv0);
        *(__half2*)op1 = __floats2half2_rn(o[jj][2] * inv1, o[jj][3] * inv1);
    }
}

// ---------------- launch ----------------
extern "C" void kernel_launch(void* const* d_in, const int* in_sizes, int n_in,
                              void* d_out, int out_size)
{
    const float* x      = (const float*)d_in[0];
    const float* ln1_w  = (const float*)d_in[1];
    const float* ln1_b  = (const float*)d_in[2];
    const float* w_qkv  = (const float*)d_in[3];
    const float* b_qkv  = (const float*)d_in[4];
    const float* w_out  = (const float*)d_in[5];
    const float* b_out  = (const float*)d_in[6];
    const float* ln2_w  = (const float*)d_in[7];
    const float* ln2_b  = (const float*)d_in[8];
    const float* w_fc   = (const float*)d_in[9];
    const float* b_fc   = (const float*)d_in[10];
    const float* w_proj = (const float*)d_in[11];
    const float* b_proj = (const float*)d_in[12];
    float* out = (float*)d_out;

    void *p_hb, *p_qkvh, *p_attnb, *p_x1, *p_fb, *p_wq, *p_wo, *p_wf, *p_wp;
    cudaGetSymbolAddress(&p_hb, g_hb);
    cudaGetSymbolAddress(&p_qkvh, g_qkvh);
    cudaGetSymbolAddress(&p_attnb, g_attnb);
    cudaGetSymbolAddress(&p_x1, g_x1);
    cudaGetSymbolAddress(&p_fb, g_fb);
    cudaGetSymbolAddress(&p_wq, g_wq);
    cudaGetSymbolAddress(&p_wo, g_wo);
    cudaGetSymbolAddress(&p_wf, g_wf);
    cudaGetSymbolAddress(&p_wp, g_wp);
    __half* hb    = (__half*)p_hb;
    __half* qkvh  = (__half*)p_qkvh;
    __half* attnb = (__half*)p_attnb;
    float*  x1b   = (float*)p_x1;
    __half* fb    = (__half*)p_fb;
    __half* wq  = (__half*)p_wq;
    __half* wo  = (__half*)p_wo;
    __half* wf  = (__half*)p_wf;
    __half* wpj = (__half*)p_wp;

    cudaFuncSetAttribute(attn_kernel, cudaFuncAttributeMaxDynamicSharedMemorySize,
                         ATTN_SMEM_BYTES);
    cudaFuncSetAttribute(tc_gemm<0, __half>, cudaFuncAttributeMaxDynamicSharedMemorySize, TCG_SMEM_BYTES);
    cudaFuncSetAttribute(tc_gemm<1, float>, cudaFuncAttributeMaxDynamicSharedMemorySize, TCG_SMEM_BYTES);
    cudaFuncSetAttribute(tc_gemm<2, __half>, cudaFuncAttributeMaxDynamicSharedMemorySize, TCG_SMEM_BYTES);

    // 0) weights -> fp16 (single launch)
    {
        int n0 = 3*EMB*EMB/4, n1 = EMB*EMB/4, n2 = 4*EMB*EMB/4, n3 = 4*EMB*EMB/4;
        int total = n0 + n1 + n2 + n3;
        cvt_all_kernel<<<(total + 255) / 256, 256>>>(
            (const float4*)w_qkv,  (__half2*)wq,  n0,
            (const float4*)w_out,  (__half2*)wo,  n1,
            (const float4*)w_fc,   (__half2*)wf,  n2,
            (const float4*)w_proj, (__half2*)wpj, n3);
    }

    // 1) h = LN1(x)  (fp16)
    ln_kernel<<<ROWS, 256>>>(x, ln1_w, ln1_b, hb);
    // 2) qkv = h @ w_qkv^T + b_qkv  (fp16 out)
    tc_gemm<0, __half><<<dim3(3*EMB/128, ROWS/128), 256, TCG_SMEM_BYTES>>>(
        hb, wq, b_qkv, nullptr, qkvh, ROWS, 3*EMB, EMB);
    // 3) attention (fp16 flash, 128q tile; fp16 out)
    attn_kernel<<<dim3(SEQ/128, BATCH*NHEAD), 256, ATTN_SMEM_BYTES>>>(qkvh, attnb);
    // 4) x1 = x + attn @ w_out^T + b_out  (fp32 out)
    tc_gemm<1, float><<<dim3(EMB/128, ROWS/128), 256, TCG_SMEM_BYTES>>>(
        attnb, wo, b_out, x, x1b, ROWS, EMB, EMB);
    // 5) h = LN2(x1)  (fp16)
    ln_kernel<<<ROWS, 256>>>(x1b, ln2_w, ln2_b, hb);
    // 6) f = QuickGELU(h @ w_fc^T + b_fc)  (fp16 out)
    tc_gemm<2, __half><<<dim3(4*EMB/128, ROWS/128), 256, TCG_SMEM_BYTES>>>(
        hb, wf, b_fc, nullptr, fb, ROWS, 4*EMB, EMB);
    // 7) out = x1 + f @ w_proj^T + b_proj  (fp32 out)
    tc_gemm<1, float><<<dim3(EMB/128, ROWS/128), 256, TCG_SMEM_BYTES>>>(
        fb, wpj, b_proj, x1b, out, ROWS, EMB, 4*EMB);
}

// round 14
// speedup vs baseline: 7.0241x; 1.0146x over previous
#include <cuda_runtime.h>
#include <cuda_fp16.h>
#include <math.h>
#include <cstdint>

#define SEQ   2048
#define BATCH 4
#define EMB   768
#define NHEAD 12
#define DH    64
#define ROWS  (SEQ*BATCH)   // 8192

// ---------------- scratch (device globals; allocation-free) ----------------
__device__ __align__(16) __half g_hb[ROWS * EMB];        // LN out (fp16)
__device__ __align__(16) __half g_qkvh[ROWS * 3 * EMB];  // qkv (fp16)
__device__ __align__(16) __half g_attnb[ROWS * EMB];     // attn out (fp16)
__device__ float g_x1[ROWS * EMB];                       // x + attn_out (fp32)
__device__ __align__(16) __half g_fb[ROWS * 4 * EMB];    // MLP hidden (fp16)
// fp16 weight copies
__device__ __align__(16) __half g_wq[3 * EMB * EMB];
__device__ __align__(16) __half g_wo[EMB * EMB];
__device__ __align__(16) __half g_wf[4 * EMB * EMB];
__device__ __align__(16) __half g_wp[4 * EMB * EMB];

// ================= helpers =================
__device__ __forceinline__ uint32_t smem_u32(const void* p) {
    uint32_t a;
    asm("{ .reg .u64 t; cvta.to.shared.u64 t, %1; cvt.u32.u64 %0, t; }" : "=r"(a) : "l"(p));
    return a;
}
__device__ __forceinline__ float ex2f(float x) {
    float y;
    asm("ex2.approx.ftz.f32 %0, %1;" : "=f"(y) : "f"(x));
    return y;
}
__device__ __forceinline__ uint32_t ex2_h2(uint32_t a) {
    uint32_t r;
    asm("ex2.approx.f16x2 %0, %1;" : "=r"(r) : "r"(a));
    return r;
}
#define CP_ASYNC16(dst, src) \
    asm volatile("cp.async.cg.shared.global [%0], [%1], 16;" :: "r"(dst), "l"(src) : "memory")
#define CP_COMMIT() asm volatile("cp.async.commit_group;" ::: "memory")
#define CP_WAITG(n) asm volatile("cp.async.wait_group %0;" :: "n"(n) : "memory")

__device__ __forceinline__ void ldmx4(uint32_t* r, uint32_t addr) {
    asm volatile("ldmatrix.sync.aligned.m8n8.x4.shared.b16 {%0,%1,%2,%3}, [%4];"
                 : "=r"(r[0]), "=r"(r[1]), "=r"(r[2]), "=r"(r[3]) : "r"(addr));
}
__device__ __forceinline__ void ldmx4t(uint32_t* r, uint32_t addr) {
    asm volatile("ldmatrix.sync.aligned.m8n8.x4.trans.shared.b16 {%0,%1,%2,%3}, [%4];"
                 : "=r"(r[0]), "=r"(r[1]), "=r"(r[2]), "=r"(r[3]) : "r"(addr));
}
__device__ __forceinline__ void mma_f16(float* c, const uint32_t* a, uint32_t b0, uint32_t b1) {
    asm volatile(
        "mma.sync.aligned.m16n8k16.row.col.f32.f16.f16.f32 "
        "{%0,%1,%2,%3}, {%4,%5,%6,%7}, {%8,%9}, {%0,%1,%2,%3};"
        : "+f"(c[0]), "+f"(c[1]), "+f"(c[2]), "+f"(c[3])
        : "r"(a[0]), "r"(a[1]), "r"(a[2]), "r"(a[3]), "r"(b0), "r"(b1));
}
__device__ __forceinline__ uint32_t h2u(float a, float b) {
    __half2 h = __floats2half2_rn(a, b);
    return *reinterpret_cast<uint32_t*>(&h);
}

// ---------------- weights fp32 -> fp16 (all four in one launch) ----------------
__global__ void cvt_all_kernel(
    const float4* __restrict__ i0, __half2* __restrict__ o0, int n0,
    const float4* __restrict__ i1, __half2* __restrict__ o1, int n1,
    const float4* __restrict__ i2, __half2* __restrict__ o2, int n2,
    const float4* __restrict__ i3, __half2* __restrict__ o3, int n3)
{
    int i = blockIdx.x * blockDim.x + threadIdx.x;
    const float4* in; __half2* out; int idx;
    if (i < n0)                { in = i0; out = o0; idx = i; }
    else if (i < n0+n1)        { in = i1; out = o1; idx = i - n0; }
    else if (i < n0+n1+n2)     { in = i2; out = o2; idx = i - n0 - n1; }
    else if (i < n0+n1+n2+n3)  { in = i3; out = o3; idx = i - n0 - n1 - n2; }
    else return;
    float4 v = in[idx];
    out[2*idx]   = __floats2half2_rn(v.x, v.y);
    out[2*idx+1] = __floats2half2_rn(v.z, v.w);
}

// ---------------- LayerNorm (fp16 out) ----------------
__inline__ __device__ float warp_sum(float v) {
    #pragma unroll
    for (int o = 16; o; o >>= 1) v += __shfl_xor_sync(0xffffffffu, v, o);
    return v;
}

__global__ void __launch_bounds__(256) ln_kernel(
    const float* __restrict__ x, const float* __restrict__ w,
    const float* __restrict__ b, __half* __restrict__ y)
{
    __shared__ float rs[8], rq[8];
    __shared__ float s_mean, s_rstd;
    int row = blockIdx.x;
    int tid = threadIdx.x;
    const float* xr = x + (size_t)row * EMB;
    float v0 = xr[tid], v1 = xr[tid + 256], v2 = xr[tid + 512];
    float s = v0 + v1 + v2;
    float q = v0*v0 + v1*v1 + v2*v2;
    s = warp_sum(s); q = warp_sum(q);
    int wid = tid >> 5, lane = tid & 31;
    if (lane == 0) { rs[wid] = s; rq[wid] = q; }
    __syncthreads();
    if (tid == 0) {
        float S = 0.f, Q = 0.f;
        #pragma unroll
        for (int i = 0; i < 8; i++) { S += rs[i]; Q += rq[i]; }
        float mean = S * (1.0f / EMB);
        float var  = Q * (1.0f / EMB) - mean * mean;
        s_mean = mean;
        s_rstd = rsqrtf(var + 1e-5f);
    }
    __syncthreads();
    float mean = s_mean, rstd = s_rstd;
    __half* yr = y + (size_t)row * EMB;
    yr[tid]       = __float2half_rn((v0 - mean) * rstd * w[tid]       + b[tid]);
    yr[tid + 256] = __float2half_rn((v1 - mean) * rstd * w[tid + 256] + b[tid + 256]);
    yr[tid + 512] = __float2half_rn((v2 - mean) * rstd * w[tid + 512] + b[tid + 512]);
}

// ---------------- fp16 mma.sync GEMM, 3-stage pipeline ----------------
#define SB    144
#define GBUF  (128 * SB)                 // 18432 B
#define TCG_SMEM_BYTES (6 * GBUF)        // 110592

template<int MODE, typename OutT>
__global__ void __launch_bounds__(256, 2) tc_gemm(
    const __half* __restrict__ A, const __half* __restrict__ B,
    const float* __restrict__ bias, const float* __restrict__ res,
    OutT* __restrict__ C, int M, int N, int K)
{
    extern __shared__ char smc[];
    uint32_t sbase = smem_u32(smc);

    int tid = threadIdx.x;
    int wp = tid >> 5, lane = tid & 31;
    int wm = wp & 1, wn = wp >> 1;

    int m0 = blockIdx.y * 128, n0 = blockIdx.x * 128;

    int rS[4], cS[4];
    #pragma unroll
    for (int i = 0; i < 4; i++) { int f = tid + 256 * i; rS[i] = f >> 3; cS[i] = f & 7; }

    const int NSTG = K >> 6;

    #pragma unroll
    for (int st = 0; st < 2; st++) {
        int k0 = st << 6;
        #pragma unroll
        for (int i = 0; i < 4; i++) {
            uint32_t so = (uint32_t)(rS[i] * SB + cS[i] * 16);
            CP_ASYNC16(sbase + (uint32_t)(st * GBUF) + so,       A + (size_t)(m0 + rS[i]) * K + k0 + cS[i] * 8);
            CP_ASYNC16(sbase + (uint32_t)((3 + st) * GBUF) + so, B + (size_t)(n0 + rS[i]) * K + k0 + cS[i] * 8);
        }
        CP_COMMIT();
    }

    float acc[4][4][4];
    #pragma unroll
    for (int mf = 0; mf < 4; mf++)
        #pragma unroll
        for (int nf = 0; nf < 4; nf++)
            #pragma unroll
            for (int r = 0; r < 4; r++) acc[mf][nf][r] = 0.f;

    uint32_t a_base = (uint32_t)((wm * 64 + (lane & 15)) * SB + (lane >> 4) * 16);
    uint32_t b_base = (uint32_t)((wn * 32 + (lane & 15)) * SB + (lane >> 4) * 16);

    for (int it = 0; it < NSTG; it++) {
        CP_WAITG(1);
        __syncthreads();
        if (it + 2 < NSTG) {
            int st = (it + 2) % 3;
            int k0 = (it + 2) << 6;
            #pragma unroll
            for (int i = 0; i < 4; i++) {
                uint32_t so = (uint32_t)(rS[i] * SB + cS[i] * 16);
                CP_ASYNC16(sbase + (uint32_t)(st * GBUF) + so,       A + (size_t)(m0 + rS[i]) * K + k0 + cS[i] * 8);
                CP_ASYNC16(sbase + (uint32_t)((3 + st) * GBUF) + so, B + (size_t)(n0 + rS[i]) * K + k0 + cS[i] * 8);
            }
        }
        CP_COMMIT();

        int cur = it % 3;
        uint32_t ab = sbase + (uint32_t)(cur * GBUF) + a_base;
        uint32_t bb = sbase + (uint32_t)((3 + cur) * GBUF) + b_base;
        #pragma unroll
        for (int ks = 0; ks < 4; ks++) {
            uint32_t afr[4][4];
            #pragma unroll
            for (int mf = 0; mf < 4; mf++)
                ldmx4(afr[mf], ab + (uint32_t)(mf * 16 * SB + ks * 32));
            uint32_t b0f[4], b1f[4];
            ldmx4(b0f, bb + (uint32_t)(ks * 32));
            ldmx4(b1f, bb + (uint32_t)(16 * SB + ks * 32));
            #pragma unroll
            for (int mf = 0; mf < 4; mf++) {
                mma_f16(acc[mf][0], afr[mf], b0f[0], b0f[2]);
                mma_f16(acc[mf][1], afr[mf], b0f[1], b0f[3]);
                mma_f16(acc[mf][2], afr[mf], b1f[0], b1f[2]);
                mma_f16(acc[mf][3], afr[mf], b1f[1], b1f[3]);
            }
        }
    }

    int g = lane >> 2, q = lane & 3;
    const __half2 H2_ONE = __floats2half2_rn(1.f, 1.f);
    #pragma unroll
    for (int mf = 0; mf < 4; mf++) {
        int r0 = m0 + wm * 64 + mf * 16 + g;
        #pragma unroll
        for (int nf = 0; nf < 4; nf++) {
            int col = n0 + wn * 32 + nf * 8 + 2 * q;
            float b0 = bias[col], b1 = bias[col + 1];
            float v0 = acc[mf][nf][0] + b0;
            float v1 = acc[mf][nf][1] + b1;
            float v2 = acc[mf][nf][2] + b0;
            float v3 = acc[mf][nf][3] + b1;
            if (MODE == 1) {
                const float* rp0 = res + (size_t)r0 * N + col;
                const float* rp1 = res + (size_t)(r0 + 8) * N + col;
                v0 += rp0[0]; v1 += rp0[1];
                v2 += rp1[0]; v3 += rp1[1];
            }
            if (MODE == 2) {
                // QuickGELU via f16x2: y = v * rcp(1 + exp2(-1.702*log2e*v))
                const float NC = -2.4554074f;  // -1.702 * log2(e)
                uint32_t e01 = ex2_h2(h2u(v0 * NC, v1 * NC));
                uint32_t e23 = ex2_h2(h2u(v2 * NC, v3 * NC));
                __half2 s01 = h2rcp(__hadd2(H2_ONE, *(__half2*)&e01));
                __half2 s23 = h2rcp(__hadd2(H2_ONE, *(__half2*)&e23));
                __half2 r01 = __hmul2(__floats2half2_rn(v0, v1), s01);
                __half2 r23 = __hmul2(__floats2half2_rn(v2, v3), s23);
                *(__half2*)((__half*)C + (size_t)r0 * N + col)       = r01;
                *(__half2*)((__half*)C + (size_t)(r0 + 8) * N + col) = r23;
            } else if (sizeof(OutT) == 2) {
                *(__half2*)((__half*)C + (size_t)r0 * N + col)       = __floats2half2_rn(v0, v1);
                *(__half2*)((__half*)C + (size_t)(r0 + 8) * N + col) = __floats2half2_rn(v2, v3);
            } else {
                *(float2*)((float*)C + (size_t)r0 * N + col)       = make_float2(v0, v1);
                *(float2*)((float*)C + (size_t)(r0 + 8) * N + col) = make_float2(v2, v3);
            }
        }
    }
}

// ---------------- fp16 mma.sync flash attention, 128q tile ----------------
// Q frags hoisted; softmax exp on ex2.f16x2 (one MUFU per 2 elems, output IS
// the P fragment); row sums l via HMMA against a ones B-fragment (no shfl tree).
#define QTILE 18432                      // 128 * 144
#define ATILE 9216                       // 64 * 144
#define ATTN_SMEM_BYTES (QTILE + 6 * ATILE)   // 73728
#define SM_SCALE_LOG2E 0.1803368801111204f    // 0.125 * log2(e)

__global__ void __launch_bounds__(256) attn_kernel(
    const __half* __restrict__ qkv, __half* __restrict__ out)
{
    extern __shared__ char sma[];
    uint32_t sb = smem_u32(sma);

    int tid = threadIdx.x;
    int w = tid >> 5, lane = tid & 31;
    int g = lane >> 2, qd = lane & 3;
    int nh = blockIdx.y;
    int n = nh / NHEAD, h = nh % NHEAD;
    int q0 = blockIdx.x * 128;

    const size_t GROW = (size_t)BATCH * 3 * EMB;

    int rQ[4], cQ[4];
    #pragma unroll
    for (int i = 0; i < 4; i++) { int f = tid + 256 * i; rQ[i] = f >> 3; cQ[i] = f & 7; }
    int rT[2], cT[2];
    #pragma unroll
    for (int i = 0; i < 2; i++) { int f = tid + 256 * i; rT[i] = f >> 3; cT[i] = f & 7; }

    const __half* qbase = qkv + ((size_t)q0 * BATCH + n) * (3 * EMB) + h * DH;
    const __half* kroot = qkv + (size_t)n * (3 * EMB) + EMB + h * DH;

    #pragma unroll
    for (int i = 0; i < 4; i++) {
        uint32_t so = (uint32_t)(rQ[i] * SB + cQ[i] * 16);
        CP_ASYNC16(sb + so, qbase + (size_t)rQ[i] * GROW + cQ[i] * 8);
    }
    #pragma unroll
    for (int i = 0; i < 2; i++) {
        uint32_t so = (uint32_t)(rT[i] * SB + cT[i] * 16);
        const __half* src = kroot + (size_t)rT[i] * GROW + cT[i] * 8;
        CP_ASYNC16(sb + (uint32_t)QTILE + so, src);
        CP_ASYNC16(sb + (uint32_t)(QTILE + 3 * ATILE) + so, src + EMB);
    }
    CP_COMMIT();
    #pragma unroll
    for (int i = 0; i < 2; i++) {
        uint32_t so = (uint32_t)(rT[i] * SB + cT[i] * 16);
        const __half* src = kroot + (size_t)(64 + rT[i]) * GROW + cT[i] * 8;
        CP_ASYNC16(sb + (uint32_t)(QTILE + ATILE) + so, src);
        CP_ASYNC16(sb + (uint32_t)(QTILE + 4 * ATILE) + so, src + EMB);
    }
    CP_COMMIT();

    const uint32_t frag = (uint32_t)((lane & 15) * SB + (lane >> 4) * 16);
    const uint32_t a_q = sb + (uint32_t)(w * 16 * SB) + frag;

    CP_WAITG(1);
    __syncthreads();
    uint32_t qf[4][4];
    #pragma unroll
    for (int kd = 0; kd < 4; kd++)
        ldmx4(qf[kd], a_q + (uint32_t)(kd * 32));

    float m0r = -1e30f, m1r = -1e30f, l0r = 0.f, l1r = 0.f;
    float o[8][4];
    #pragma unroll
    for (int i = 0; i < 8; i++)
        #pragma unroll
        for (int j = 0; j < 4; j++) o[i][j] = 0.f;

    const uint32_t ONES = 0x3C003C00u;   // half2(1,1)
    const int NT = SEQ / 64;
    for (int t = 0; t < NT; t++) {
        CP_WAITG(1);
        __syncthreads();
        if (t + 2 < NT) {
            int st = (t + 2) % 3;
            const __half* kb = kroot + (size_t)((t + 2) * 64) * GROW;
            #pragma unroll
            for (int i = 0; i < 2; i++) {
                uint32_t so = (uint32_t)(rT[i] * SB + cT[i] * 16);
                const __half* src = kb + (size_t)rT[i] * GROW + cT[i] * 8;
                CP_ASYNC16(sb + (uint32_t)(QTILE + st * ATILE) + so, src);
                CP_ASYNC16(sb + (uint32_t)(QTILE + (3 + st) * ATILE) + so, src + EMB);
            }
        }
        CP_COMMIT();

        int cur = t % 3;
        uint32_t kbuf = sb + (uint32_t)(QTILE + cur * ATILE);
        uint32_t vbuf = sb + (uint32_t)(QTILE + (3 + cur) * ATILE);

        // S = Q @ K^T (raw)
        float s4[8][4];
        #pragma unroll
        for (int i = 0; i < 8; i++)
            #pragma unroll
            for (int j = 0; j < 4; j++) s4[i][j] = 0.f;
        #pragma unroll
        for (int kd = 0; kd < 4; kd++) {
            #pragma unroll
            for (int j = 0; j < 4; j++) {
                uint32_t bk[4];
                ldmx4(bk, kbuf + (uint32_t)(j * 16 * SB + kd * 32) + frag);
                mma_f16(s4[2*j+0], qf[kd], bk[0], bk[2]);
                mma_f16(s4[2*j+1], qf[kd], bk[1], bk[3]);
            }
        }

        // online softmax (max over raw S; folded scale in exponent)
        float rm0 = -1e30f, rm1 = -1e30f;
        #pragma unroll
        for (int i = 0; i < 8; i++) {
            rm0 = fmaxf(rm0, fmaxf(s4[i][0], s4[i][1]));
            rm1 = fmaxf(rm1, fmaxf(s4[i][2], s4[i][3]));
        }
        rm0 = fmaxf(rm0, __shfl_xor_sync(0xffffffffu, rm0, 1));
        rm0 = fmaxf(rm0, __shfl_xor_sync(0xffffffffu, rm0, 2));
        rm1 = fmaxf(rm1, __shfl_xor_sync(0xffffffffu, rm1, 1));
        rm1 = fmaxf(rm1, __shfl_xor_sync(0xffffffffu, rm1, 2));
        float mn0 = fmaxf(m0r, rm0), mn1 = fmaxf(m1r, rm1);
        float f0 = ex2f((m0r - mn0) * SM_SCALE_LOG2E);
        float f1 = ex2f((m1r - mn1) * SM_SCALE_LOG2E);
        m0r = mn0; m1r = mn1;
        float nm0 = -mn0 * SM_SCALE_LOG2E, nm1 = -mn1 * SM_SCALE_LOG2E;

        // P fragments directly from f16x2 ex2
        uint32_t pa[4][4];
        #pragma unroll
        for (int j = 0; j < 4; j++) {
            pa[j][0] = ex2_h2(h2u(fmaf(s4[2*j+0][0], SM_SCALE_LOG2E, nm0),
                                  fmaf(s4[2*j+0][1], SM_SCALE_LOG2E, nm0)));
            pa[j][1] = ex2_h2(h2u(fmaf(s4[2*j+0][2], SM_SCALE_LOG2E, nm1),
                                  fmaf(s4[2*j+0][3], SM_SCALE_LOG2E, nm1)));
            pa[j][2] = ex2_h2(h2u(fmaf(s4[2*j+1][0], SM_SCALE_LOG2E, nm0),
                                  fmaf(s4[2*j+1][1], SM_SCALE_LOG2E, nm0)));
            pa[j][3] = ex2_h2(h2u(fmaf(s4[2*j+1][2], SM_SCALE_LOG2E, nm1),
                                  fmaf(s4[2*j+1][3], SM_SCALE_LOG2E, nm1)));
        }

        // row sums via HMMA: P @ ones  (sums over k, across quad lanes, fp32)
        float sacc[4] = {0.f, 0.f, 0.f, 0.f};
        #pragma unroll
        for (int ks = 0; ks < 4; ks++)
            mma_f16(sacc, pa[ks], ONES, ONES);
        l0r = l0r * f0 + sacc[0];
        l1r = l1r * f1 + sacc[2];

        #pragma unroll
        for (int i = 0; i < 8; i++) {
            o[i][0] *= f0; o[i][1] *= f0; o[i][2] *= f1; o[i][3] *= f1;
        }

        // O += P @ V
        #pragma unroll
        for (int ks = 0; ks < 4; ks++) {
            #pragma unroll
            for (int t4 = 0; t4 < 4; t4++) {
                uint32_t bv[4];
                ldmx4t(bv, vbuf + (uint32_t)(ks * 16 * SB + t4 * 32) + frag);
                mma_f16(o[2*t4+0], pa[ks], bv[0], bv[1]);
                mma_f16(o[2*t4+1], pa[ks], bv[2], bv[3]);
            }
        }
    }

    // epilogue (fp16 out)
    float inv0 = 1.0f / l0r, inv1 = 1.0f / l1r;
    int row0 = q0 + w * 16 + g;
    #pragma unroll
    for (int jj = 0; jj < 8; jj++) {
        int col = jj * 8 + 2 * qd;
        __half* op0 = out + ((size_t)row0 * BATCH + n) * EMB + h * DH + col;
        __half* op1 = out + ((size_t)(row0 + 8) * BATCH + n) * EMB + h * DH + col;
        *(__half2*)op0 = __floats2half2_rn(o[jj][0] * inv0, o[jj][1] * inv0);
        *(__half2*)op1 = __floats2half2_rn(o[jj][2] * inv1, o[jj][3] * inv1);
    }
}

// ---------------- launch ----------------
extern "C" void kernel_launch(void* const* d_in, const int* in_sizes, int n_in,
                              void* d_out, int out_size)
{
    const float* x      = (const float*)d_in[0];
    const float* ln1_w  = (const float*)d_in[1];
    const float* ln1_b  = (const float*)d_in[2];
    const float* w_qkv  = (const float*)d_in[3];
    const float* b_qkv  = (const float*)d_in[4];
    const float* w_out  = (const float*)d_in[5];
    const float* b_out  = (const float*)d_in[6];
    const float* ln2_w  = (const float*)d_in[7];
    const float* ln2_b  = (const float*)d_in[8];
    const float* w_fc   = (const float*)d_in[9];
    const float* b_fc   = (const float*)d_in[10];
    const float* w_proj = (const float*)d_in[11];
    const float* b_proj = (const float*)d_in[12];
    float* out = (float*)d_out;

    void *p_hb, *p_qkvh, *p_attnb, *p_x1, *p_fb, *p_wq, *p_wo, *p_wf, *p_wp;
    cudaGetSymbolAddress(&p_hb, g_hb);
    cudaGetSymbolAddress(&p_qkvh, g_qkvh);
    cudaGetSymbolAddress(&p_attnb, g_attnb);
    cudaGetSymbolAddress(&p_x1, g_x1);
    cudaGetSymbolAddress(&p_fb, g_fb);
    cudaGetSymbolAddress(&p_wq, g_wq);
    cudaGetSymbolAddress(&p_wo, g_wo);
    cudaGetSymbolAddress(&p_wf, g_wf);
    cudaGetSymbolAddress(&p_wp, g_wp);
    __half* hb    = (__half*)p_hb;
    __half* qkvh  = (__half*)p_qkvh;
    __half* attnb = (__half*)p_attnb;
    float*  x1b   = (float*)p_x1;
    __half* fb    = (__half*)p_fb;
    __half* wq  = (__half*)p_wq;
    __half* wo  = (__half*)p_wo;
    __half* wf  = (__half*)p_wf;
    __half* wpj = (__half*)p_wp;

    cudaFuncSetAttribute(attn_kernel, cudaFuncAttributeMaxDynamicSharedMemorySize,
                         ATTN_SMEM_BYTES);
    cudaFuncSetAttribute(tc_gemm<0, __half>, cudaFuncAttributeMaxDynamicSharedMemorySize, TCG_SMEM_BYTES);
    cudaFuncSetAttribute(tc_gemm<1, float>, cudaFuncAttributeMaxDynamicSharedMemorySize, TCG_SMEM_BYTES);
    cudaFuncSetAttribute(tc_gemm<2, __half>, cudaFuncAttributeMaxDynamicSharedMemorySize, TCG_SMEM_BYTES);

    // 0) weights -> fp16 (single launch)
    {
        int n0 = 3*EMB*EMB/4, n1 = EMB*EMB/4, n2 = 4*EMB*EMB/4, n3 = 4*EMB*EMB/4;
        int total = n0 + n1 + n2 + n3;
        cvt_all_kernel<<<(total + 255) / 256, 256>>>(
            (const float4*)w_qkv,  (__half2*)wq,  n0,
            (const float4*)w_out,  (__half2*)wo,  n1,
            (const float4*)w_fc,   (__half2*)wf,  n2,
            (const float4*)w_proj, (__half2*)wpj, n3);
    }

    // 1) h = LN1(x)  (fp16)
    ln_kernel<<<ROWS, 256>>>(x, ln1_w, ln1_b, hb);
    // 2) qkv = h @ w_qkv^T + b_qkv  (fp16 out)
    tc_gemm<0, __half><<<dim3(3*EMB/128, ROWS/128), 256, TCG_SMEM_BYTES>>>(
        hb, wq, b_qkv, nullptr, qkvh, ROWS, 3*EMB, EMB);
    // 3) attention (fp16 flash, 128q tile; fp16 out)
    attn_kernel<<<dim3(SEQ/128, BATCH*NHEAD), 256, ATTN_SMEM_BYTES>>>(qkvh, attnb);
    // 4) x1 = x + attn @ w_out^T + b_out  (fp32 out)
    tc_gemm<1, float><<<dim3(EMB/128, ROWS/128), 256, TCG_SMEM_BYTES>>>(
        attnb, wo, b_out, x, x1b, ROWS, EMB, EMB);
    // 5) h = LN2(x1)  (fp16)
    ln_kernel<<<ROWS, 256>>>(x1b, ln2_w, ln2_b, hb);
    // 6) f = QuickGELU(h @ w_fc^T + b_fc)  (fp16 out)
    tc_gemm<2, __half><<<dim3(4*EMB/128, ROWS/128), 256, TCG_SMEM_BYTES>>>(
        hb, wf, b_fc, nullptr, fb, ROWS, 4*EMB, EMB);
    // 7) out = x1 + f @ w_proj^T + b_proj  (fp32 out)
    tc_gemm<1, float><<<dim3(EMB/128, ROWS/128), 256, TCG_SMEM_BYTES>>>(
        fb, wpj, b_proj, x1b, out, ROWS, EMB, 4*EMB);
}